// round 14
// baseline (speedup 1.0000x reference)
#include <cuda_runtime.h>
#include <math.h>

#define BATCH 16
#define SEQ   512
#define NDIM  32
#define NMAT  (BATCH*SEQ)     // 8192
#define FDIM  (NDIM*NDIM)     // 1024
#define FP    512             // padded packed feature dim

typedef unsigned long long u64;

// ---- packed f32x2 helpers ---------------------------------------------------
__device__ __forceinline__ u64 pack2(float lo, float hi) {
    u64 r; asm("mov.b64 %0, {%1, %2};" : "=l"(r) : "f"(lo), "f"(hi)); return r;
}
__device__ __forceinline__ u64 dup2(float v) {
    u64 r; asm("mov.b64 %0, {%1, %1};" : "=l"(r) : "f"(v)); return r;
}
__device__ __forceinline__ float2 unpack2(u64 v) {
    float2 f; asm("mov.b64 {%0, %1}, %2;" : "=f"(f.x), "=f"(f.y) : "l"(v)); return f;
}
#define FFMA2(acc, a2, b2) asm("fma.rn.f32x2 %0, %1, %2, %0;" : "+l"(acc) : "l"(a2), "l"(b2))
#define FMUL2I(g, s2)      asm("mul.rn.f32x2 %0, %0, %1;"     : "+l"(g)   : "l"(s2))
#define FADD2(d, a, b)     asm("add.rn.f32x2 %0, %1, %2;"     : "=l"(d)   : "l"(a), "l"(b))

// ---------------- scratch (static __device__, zero-initialized) ---------------
__device__ float d_qp[NMAT*FP];            // packed sqrt(2)*q lower-tri (pad 0)
__device__ float d_kp[NMAT*FP];            // packed sqrt(2)*k lower-tri (pad 0)
__device__ float d_vp[NMAT*FP];            // packed v lower-tri (pad 0)
__device__ float d_outp[NMAT*FP];          // packed output
__device__ float d_sc[BATCH*SEQ*SEQ];      // exp(scores)
__device__ float d_part[4*BATCH*SEQ];      // per-rowtile partial colsums
__device__ float d_isum[BATCH*SEQ];        // 1/colsum of exp
__device__ float d_C [3*FDIM];             // cayley matrices for q,k,v
__device__ float d_q2[NMAT];
__device__ float d_k2[NMAT];

// ---------------- Cayley (one warp, one weight): C = (I-X)(I+X)^-1 ------------
__device__ void cayley_one(const float* __restrict__ W, float* __restrict__ Cout,
                           float (*Aug)[65], int lane) {
    for (int r = 0; r < 32; r++) {
        float xv = W[r*32 + lane] - W[lane*32 + r];
        float id = (r == lane) ? 1.f : 0.f;
        Aug[r][lane]      = id - xv;
        Aug[r][32 + lane] = id + xv;
    }
    __syncwarp();
    for (int kp = 0; kp < 32; kp++) {
        float ip = 1.f / Aug[kp][kp];
        __syncwarp();
        Aug[kp][lane]      *= ip;
        Aug[kp][32 + lane] *= ip;
        __syncwarp();
        for (int r = 0; r < 32; r++) {
            if (r == kp) continue;
            float f = Aug[r][kp];
            Aug[r][lane]      = fmaf(-f, Aug[kp][lane],      Aug[r][lane]);
            Aug[r][32 + lane] = fmaf(-f, Aug[kp][32 + lane], Aug[r][32 + lane]);
        }
        __syncwarp();
    }
    for (int i = 0; i < 32; i++)
        Cout[i*32 + lane] = Aug[lane][32 + i];
}

__global__ void __launch_bounds__(128) cayley_kernel(
        const float* __restrict__ qw, const float* __restrict__ kw,
        const float* __restrict__ vw) {
    __shared__ float Aug[3][32][65];
    const int lane = threadIdx.x & 31;
    const int wip  = threadIdx.x >> 5;
    if (wip < 3) {
        const float* W = (wip == 0) ? qw : (wip == 1) ? kw : vw;
        cayley_one(W, d_C + wip*FDIM, Aug[wip], lane);
    }
}

// ---------------- fused jacobi logm + transform, 128-thr blocks ---------------
#define CSTR 36
__global__ void __launch_bounds__(128, 6) jacobi_transform_kernel(
        const float* __restrict__ x) {
    __shared__ __align__(16) u64  GT[4][32][17];    // Gp, then Ts overlay (per warp)
    __shared__ float Al[4][32];
    __shared__ __align__(16) float Ct[3][32][CSTR]; // Ct[w][k][i] = C_w[i][k]
    const int lane = threadIdx.x & 31;
    const int wip  = threadIdx.x >> 5;
    const unsigned FULL = 0xffffffffu;
    const int m = blockIdx.x * 4 + wip;
    const float* A = x + (size_t)m * FDIM;

    for (int idx = threadIdx.x; idx < 3*1024; idx += 128) {
        int w = idx >> 10, rem = idx & 1023, i = rem >> 5, k = rem & 31;
        Ct[w][k][i] = d_C[w*FDIM + i*32 + k];
    }
    __syncthreads();

    u64 g2[16];
#pragma unroll
    for (int r = 0; r < 16; r++)
        g2[r] = pack2(A[(2*r)*32 + lane], A[(2*r+1)*32 + lane]);

    float nrm;
    {
        u64 nA = 0ull, nB = 0ull, nC = 0ull, nD = 0ull;
#pragma unroll
        for (int r = 0; r < 4; r++) {
            FFMA2(nA, g2[r],      g2[r]);
            FFMA2(nB, g2[4 + r],  g2[4 + r]);
            FFMA2(nC, g2[8 + r],  g2[8 + r]);
            FFMA2(nD, g2[12 + r], g2[12 + r]);
        }
        u64 s; FADD2(s, nA, nB); u64 t2; FADD2(t2, nC, nD); FADD2(s, s, t2);
        float2 nf = unpack2(s);
        nrm = nf.x + nf.y;
    }
    float scale = 1.f, iscale = 1.f;

    for (int sweep = 0; sweep < 6; sweep++) {
        bool big = false;
        for (int mm = 1; mm < 32; mm++) {
            const int partner = lane ^ mm;
            u64 h2[16];
#pragma unroll
            for (int r = 0; r < 16; r++) h2[r] = __shfl_xor_sync(FULL, g2[r], mm);
            u64 dA = 0ull, dB = 0ull, dC = 0ull, dD = 0ull;
#pragma unroll
            for (int r = 0; r < 4; r++) {
                FFMA2(dA, g2[r],      h2[r]);
                FFMA2(dB, g2[4 + r],  h2[4 + r]);
                FFMA2(dC, g2[8 + r],  h2[8 + r]);
                FFMA2(dD, g2[12 + r], h2[12 + r]);
            }
            u64 ds; FADD2(ds, dA, dB); u64 dt; FADD2(dt, dC, dD); FADD2(ds, ds, dt);
            float2 df = unpack2(ds);
            float dotv = df.x + df.y;
            float nrm_o = __shfl_xor_sync(FULL, nrm,   mm);
            float sc_o  = __shfl_xor_sync(FULL, scale, mm);
            float apq = dotv * scale * sc_o;
            const bool is_p = lane < partner;
            float app = is_p ? nrm : nrm_o;
            float aqq = is_p ? nrm_o : nrm;
            float prod = app * aqq;
            float c2v  = apq * apq;
            big = big || (c2v > 1e-4f * prod);
            bool rot = (c2v > 1e-8f * prod);
            unsigned ball = __ballot_sync(FULL, rot);
            if (ball) {
                if (rot) {
                    float tau = (aqq - app) * 0.5f / apq;
                    float t   = copysignf(1.f, tau) / (fabsf(tau) + sqrtf(fmaf(tau, tau, 1.f)));
                    float u   = fmaf(t, t, 1.f);
                    float cc  = rsqrtf(u);
                    float rc  = sqrtf(u);
                    float spt = is_p ? -t : t;
                    u64 c2 = dup2(spt * sc_o * iscale);
#pragma unroll
                    for (int r = 0; r < 16; r++) FFMA2(g2[r], c2, h2[r]);
                    nrm = fmaf(spt, apq, nrm);
                    scale *= cc; iscale *= rc;
                }
            }
        }
        u64 s2 = dup2(scale);
#pragma unroll
        for (int r = 0; r < 16; r++) FMUL2I(g2[r], s2);
        scale = 1.f; iscale = 1.f;
        if (!__any_sync(FULL, big)) break;
    }

    float nx;
    {
        u64 nA = 0ull, nB = 0ull, nC = 0ull, nD = 0ull;
#pragma unroll
        for (int r = 0; r < 4; r++) {
            FFMA2(nA, g2[r],      g2[r]);
            FFMA2(nB, g2[4 + r],  g2[4 + r]);
            FFMA2(nC, g2[8 + r],  g2[8 + r]);
            FFMA2(nD, g2[12 + r], g2[12 + r]);
        }
        u64 s; FADD2(s, nA, nB); u64 t2; FADD2(t2, nC, nD); FADD2(s, s, t2);
        float2 xf = unpack2(s);
        nx = xf.x + xf.y;
    }
    float alpha = 0.5f * logf(nx) / nx;

    // ---- rank-1 reconstruction via packed u64 shared columns ----
    u64* myG = &GT[wip][lane][0];
#pragma unroll
    for (int r = 0; r < 16; r++) myG[r] = g2[r];
    Al[wip][lane] = alpha;
    __syncwarp();

    u64 acc[16];
#pragma unroll
    for (int r = 0; r < 16; r++) acc[r] = 0ull;
#pragma unroll 4
    for (int t = 0; t < 32; t++) {
        const u64* col = &GT[wip][t][0];
        float2 gf = unpack2(col[lane >> 1]);
        float gelem = (lane & 1) ? gf.y : gf.x;
        u64 coef = dup2(Al[wip][t] * gelem);
#pragma unroll
        for (int r = 0; r < 16; r++) {
            u64 cv = col[r];
            FFMA2(acc[r], coef, cv);
        }
    }
    {
        float2 e = unpack2(acc[lane >> 1]);
        if (lane & 1) e.y = 0.f; else e.x = 0.f;
        acc[lane >> 1] = pack2(e.x, e.y);
    }
    __syncwarp();

    // ---- transform phase: y_w = C_w * X * C_w^T, X columns in acc ----
    for (int w = 0; w < 3; w++) {
        u64 accT[16];
#pragma unroll
        for (int r = 0; r < 16; r++) accT[r] = 0ull;
#pragma unroll
        for (int k = 0; k < 32; k++) {
            float2 xe = unpack2(acc[k >> 1]);
            u64 c2 = dup2((k & 1) ? xe.y : xe.x);
            const ulonglong2* crow = (const ulonglong2*)&Ct[w][k][0];
#pragma unroll
            for (int p = 0; p < 8; p++) {
                ulonglong2 cv = crow[p];
                FFMA2(accT[2*p],   c2, cv.x);
                FFMA2(accT[2*p+1], c2, cv.y);
            }
        }
        __syncwarp();
#pragma unroll
        for (int r = 0; r < 16; r++) GT[wip][lane][r] = accT[r];
        __syncwarp();

        u64 acy[16];
#pragma unroll
        for (int r = 0; r < 16; r++) acy[r] = 0ull;
#pragma unroll
        for (int k = 0; k < 32; k++) {
            u64 c2 = dup2(Ct[w][k][lane]);
#pragma unroll
            for (int r = 0; r < 16; r++) {
                u64 tv = GT[wip][k][r];
                FFMA2(acy[r], c2, tv);
            }
        }

        float y[32];
#pragma unroll
        for (int r = 0; r < 16; r++) {
            float2 t = unpack2(acy[r]);
            y[2*r] = t.x; y[2*r+1] = t.y;
        }
        float* dst = (w == 0) ? d_qp : (w == 1) ? d_kp : d_vp;
        const float fac = (w < 2) ? 1.41421356237f : 1.f;
        float s = 0.f;
#pragma unroll
        for (int i = 1; i < 32; i++) {
            if (lane < i) {
                float yv = y[i];
                dst[(size_t)m*FP + i*(i-1)/2 + lane] = fac * yv;
                s = fmaf(yv, yv, s);
            }
        }
        if (w < 2) {
#pragma unroll
            for (int off = 16; off; off >>= 1) s += __shfl_down_sync(0xffffffffu, s, off);
            if (lane == 0) { if (w == 0) d_q2[m] = 2.f*s; else d_k2[m] = 2.f*s; }
        }
        __syncwarp();
    }
}

// ---------------- scores GEMM 128x128xK(512 packed), f32x2, fused colsum -----
__global__ void __launch_bounds__(256, 2) scores_kernel() {
    const int b  = blockIdx.z;
    const int mt = blockIdx.y * 128;
    const int nt = blockIdx.x * 128;
    const float* Ab = d_kp + (size_t)b * SEQ * FP;
    const float* Bb = d_qp + (size_t)b * SEQ * FP;
    __shared__ __align__(16) float As[2][16][132];
    __shared__ __align__(16) float Bs[2][16][132];
    __shared__ float Ssum[16][128];
    const int tid = threadIdx.x;
    const int lr = tid >> 2, lc = (tid & 3) << 2;
    const int tx = tid & 15, ty = tid >> 4;
    const int m0 = ty << 3;
    const int nA = tx << 2;
    const int nB = 64 + (tx << 2);

    u64 acc2[8][4];
#pragma unroll
    for (int ii = 0; ii < 8; ii++)
#pragma unroll
        for (int p = 0; p < 4; p++) acc2[ii][p] = 0ull;

    const float* ap0 = Ab + (size_t)(mt + lr) * FP + lc;
    const float* ap1 = ap0 + (size_t)64 * FP;
    const float* bp0 = Bb + (size_t)(nt + lr) * FP + lc;
    const float* bp1 = bp0 + (size_t)64 * FP;

    {
        float4 a0 = *(const float4*)ap0, a1 = *(const float4*)ap1;
        float4 b0 = *(const float4*)bp0, b1 = *(const float4*)bp1;
        As[0][lc+0][lr]=a0.x; As[0][lc+1][lr]=a0.y; As[0][lc+2][lr]=a0.z; As[0][lc+3][lr]=a0.w;
        As[0][lc+0][lr+64]=a1.x; As[0][lc+1][lr+64]=a1.y; As[0][lc+2][lr+64]=a1.z; As[0][lc+3][lr+64]=a1.w;
        Bs[0][lc+0][lr]=b0.x; Bs[0][lc+1][lr]=b0.y; Bs[0][lc+2][lr]=b0.z; Bs[0][lc+3][lr]=b0.w;
        Bs[0][lc+0][lr+64]=b1.x; Bs[0][lc+1][lr+64]=b1.y; Bs[0][lc+2][lr+64]=b1.z; Bs[0][lc+3][lr+64]=b1.w;
    }
    __syncthreads();

    int buf = 0;
#pragma unroll 1
    for (int kt = 0; kt < FP; kt += 16) {
        float4 na0, na1, nb0, nb1;
        const bool more = (kt + 16 < FP);
        if (more) {
            na0 = *(const float4*)(ap0 + kt + 16);
            na1 = *(const float4*)(ap1 + kt + 16);
            nb0 = *(const float4*)(bp0 + kt + 16);
            nb1 = *(const float4*)(bp1 + kt + 16);
        }
#pragma unroll
        for (int kk = 0; kk < 16; kk++) {
            float a[8];
            *(float4*)(a)     = *(const float4*)&As[buf][kk][m0];
            *(float4*)(a + 4) = *(const float4*)&As[buf][kk][m0 + 4];
            ulonglong2 bu0 = *(const ulonglong2*)&Bs[buf][kk][nA];
            ulonglong2 bu1 = *(const ulonglong2*)&Bs[buf][kk][nB];
#pragma unroll
            for (int ii = 0; ii < 8; ii++) {
                u64 a2 = dup2(a[ii]);
                FFMA2(acc2[ii][0], a2, bu0.x);
                FFMA2(acc2[ii][1], a2, bu0.y);
                FFMA2(acc2[ii][2], a2, bu1.x);
                FFMA2(acc2[ii][3], a2, bu1.y);
            }
        }
        if (more) {
            const int nb = buf ^ 1;
            As[nb][lc+0][lr]=na0.x; As[nb][lc+1][lr]=na0.y; As[nb][lc+2][lr]=na0.z; As[nb][lc+3][lr]=na0.w;
            As[nb][lc+0][lr+64]=na1.x; As[nb][lc+1][lr+64]=na1.y; As[nb][lc+2][lr+64]=na1.z; As[nb][lc+3][lr+64]=na1.w;
            Bs[nb][lc+0][lr]=nb0.x; Bs[nb][lc+1][lr]=nb0.y; Bs[nb][lc+2][lr]=nb0.z; Bs[nb][lc+3][lr]=nb0.w;
            Bs[nb][lc+0][lr+64]=nb1.x; Bs[nb][lc+1][lr+64]=nb1.y; Bs[nb][lc+2][lr+64]=nb1.z; Bs[nb][lc+3][lr+64]=nb1.w;
        }
        __syncthreads();
        buf ^= 1;
    }

    float q2c[8];
#pragma unroll
    for (int jj = 0; jj < 4; jj++) q2c[jj]     = d_q2[b*SEQ + nt + nA + jj];
#pragma unroll
    for (int jj = 0; jj < 4; jj++) q2c[4 + jj] = d_q2[b*SEQ + nt + nB + jj];
    float csum[8];
#pragma unroll
    for (int jj = 0; jj < 8; jj++) csum[jj] = 0.f;
#pragma unroll
    for (int ii = 0; ii < 8; ii++) {
        float k2r = d_k2[b*SEQ + mt + m0 + ii];
        float o[8];
#pragma unroll
        for (int p = 0; p < 4; p++) {
            float2 ab = unpack2(acc2[ii][p]);
            float d2a = fmaxf(k2r + q2c[2*p]   - 2.f * ab.x, 1e-12f);
            float d2b = fmaxf(k2r + q2c[2*p+1] - 2.f * ab.y, 1e-12f);
            o[2*p]   = __expf(1.f / (1.f + __logf(1.f + sqrtf(d2a))));
            o[2*p+1] = __expf(1.f / (1.f + __logf(1.f + sqrtf(d2b))));
        }
#pragma unroll
        for (int jj = 0; jj < 8; jj++) csum[jj] += o[jj];
        float* row = d_sc + ((size_t)b*SEQ + mt + m0 + ii)*SEQ + nt;
        *(float4*)(row + nA) = make_float4(o[0], o[1], o[2], o[3]);
        *(float4*)(row + nB) = make_float4(o[4], o[5], o[6], o[7]);
    }
    *(float4*)&Ssum[ty][nA] = make_float4(csum[0], csum[1], csum[2], csum[3]);
    *(float4*)&Ssum[ty][nB] = make_float4(csum[4], csum[5], csum[6], csum[7]);
    __syncthreads();
    if (tid < 128) {
        float s = 0.f;
#pragma unroll
        for (int t = 0; t < 16; t++) s += Ssum[t][tid];
        d_part[(blockIdx.y * BATCH + b) * SEQ + nt + tid] = s;
    }
}

// ---------------- finalize colsum: 1/sum of 4 partials -----------------------
__global__ void softsum2_kernel() {
    const int i = blockIdx.x * 128 + threadIdx.x;
    float s = d_part[i] + d_part[BATCH*SEQ + i]
            + d_part[2*BATCH*SEQ + i] + d_part[3*BATCH*SEQ + i];
    d_isum[i] = 1.f / s;
}

// ---------------- out GEMM 128x128x16 over packed N=512, f32x2 ---------------
__global__ void __launch_bounds__(256) out_kernel() {
    const int b  = blockIdx.z;
    const int mt = blockIdx.y * 128;
    const int nt = blockIdx.x * 128;
    const float* Ab = d_sc + (size_t)b * SEQ * SEQ;
    const float* Bb = d_vp + (size_t)b * SEQ * FP;
    const float* isum = d_isum + b * SEQ;
    __shared__ __align__(16) float As[2][16][132];
    __shared__ __align__(16) float Bs[2][16][132];
    const int tid = threadIdx.x;
    const int lr = tid >> 2, lc = (tid & 3) << 2;
    const int br = tid >> 5, bc = (tid & 31) << 2;
    const int tx = tid & 15, ty = tid >> 4;
    const int m0 = ty << 3;
    const int nA = tx << 2;
    const int nB = 64 + (tx << 2);

    u64 acc2[8][4];
#pragma unroll
    for (int ii = 0; ii < 8; ii++)
#pragma unroll
        for (int p = 0; p < 4; p++) acc2[ii][p] = 0ull;

    const float* ap0 = Ab + (size_t)(mt + lr) * SEQ + lc;
    const float* ap1 = ap0 + (size_t)64 * SEQ;
    const float* bq0 = Bb + (size_t)br * FP + nt + bc;
    const float* bq1 = bq0 + (size_t)8 * FP;

    {
        float4 a0 = *(const float4*)ap0, a1 = *(const float4*)ap1;
        float4 v0 = *(const float4*)bq0, v1 = *(const float4*)bq1;
        float s0 = isum[br], s1 = isum[br + 8];
        As[0][lc+0][lr]=a0.x; As[0][lc+1][lr]=a0.y; As[0][lc+2][lr]=a0.z; As[0][lc+3][lr]=a0.w;
        As[0][lc+0][lr+64]=a1.x; As[0][lc+1][lr+64]=a1.y; As[0][lc+2][lr+64]=a1.z; As[0][lc+3][lr+64]=a1.w;
        *(float4*)&Bs[0][br][bc]   = make_float4(v0.x*s0, v0.y*s0, v0.z*s0, v0.w*s0);
        *(float4*)&Bs[0][br+8][bc] = make_float4(v1.x*s1, v1.y*s1, v1.z*s1, v1.w*s1);
    }
    __syncthreads();

    int buf = 0;
#pragma unroll 1
    for (int kt = 0; kt < SEQ; kt += 16) {
        float4 na0, na1, nv0, nv1;
        float s0 = 0.f, s1 = 0.f;
        const bool more = (kt + 16 < SEQ);
        if (more) {
            na0 = *(const float4*)(ap0 + kt + 16);
            na1 = *(const float4*)(ap1 + kt + 16);
            nv0 = *(const float4*)(bq0 + (size_t)(kt + 16) * FP);
            nv1 = *(const float4*)(bq1 + (size_t)(kt + 16) * FP);
            s0 = isum[kt + 16 + br];
            s1 = isum[kt + 16 + br + 8];
        }
#pragma unroll
        for (int kk = 0; kk < 16; kk++) {
            float a[8];
            *(float4*)(a)     = *(const float4*)&As[buf][kk][m0];
            *(float4*)(a + 4) = *(const float4*)&As[buf][kk][m0 + 4];
            ulonglong2 bu0 = *(const ulonglong2*)&Bs[buf][kk][nA];
            ulonglong2 bu1 = *(const ulonglong2*)&Bs[buf][kk][nB];
#pragma unroll
            for (int ii = 0; ii < 8; ii++) {
                u64 a2 = dup2(a[ii]);
                FFMA2(acc2[ii][0], a2, bu0.x);
                FFMA2(acc2[ii][1], a2, bu0.y);
                FFMA2(acc2[ii][2], a2, bu1.x);
                FFMA2(acc2[ii][3], a2, bu1.y);
            }
        }
        if (more) {
            const int nb = buf ^ 1;
            As[nb][lc+0][lr]=na0.x; As[nb][lc+1][lr]=na0.y; As[nb][lc+2][lr]=na0.z; As[nb][lc+3][lr]=na0.w;
            As[nb][lc+0][lr+64]=na1.x; As[nb][lc+1][lr+64]=na1.y; As[nb][lc+2][lr+64]=na1.z; As[nb][lc+3][lr+64]=na1.w;
            *(float4*)&Bs[nb][br][bc]   = make_float4(nv0.x*s0, nv0.y*s0, nv0.z*s0, nv0.w*s0);
            *(float4*)&Bs[nb][br+8][bc] = make_float4(nv1.x*s1, nv1.y*s1, nv1.z*s1, nv1.w*s1);
        }
        __syncthreads();
        buf ^= 1;
    }

#pragma unroll
    for (int ii = 0; ii < 8; ii++) {
        float* dst = d_outp + ((size_t)b*SEQ + mt + m0 + ii)*FP + nt;
        ulonglong2 s0; s0.x = acc2[ii][0]; s0.y = acc2[ii][1];
        ulonglong2 s1; s1.x = acc2[ii][2]; s1.y = acc2[ii][3];
        *(ulonglong2*)(dst + nA) = s0;
        *(ulonglong2*)(dst + nB) = s1;
    }
}

// ---------------- unpack: packed 496 -> full symmetric 32x32, diag 0 ---------
__global__ void __launch_bounds__(256) unpack_kernel(float* __restrict__ out) {
    const int m = blockIdx.x;
    const float* src = d_outp + (size_t)m * FP;
    float* dst = out + (size_t)m * FDIM;
#pragma unroll
    for (int e = 0; e < 4; e++) {
        const int idx = threadIdx.x + e * 256;
        const int i = idx >> 5, j = idx & 31;
        float v = 0.f;
        if (i != j) {
            const int hi = (i > j) ? i : j;
            const int lo = (i > j) ? j : i;
            v = src[hi*(hi-1)/2 + lo];
        }
        dst[idx] = v;
    }
}

// ---------------- launch ----------------------------------------------------
extern "C" void kernel_launch(void* const* d_in, const int* in_sizes, int n_in,
                              void* d_out, int out_size) {
    (void)in_sizes; (void)n_in; (void)out_size;
    const float* x  = (const float*)d_in[0];
    const float* qw = (const float*)d_in[1];
    const float* kw = (const float*)d_in[2];
    const float* vw = (const float*)d_in[3];
    float* out = (float*)d_out;

    cayley_kernel<<<1, 128>>>(qw, kw, vw);
    jacobi_transform_kernel<<<NMAT/4, 128>>>(x);
    scores_kernel<<<dim3(SEQ/128, SEQ/128, BATCH), 256>>>();
    softsum2_kernel<<<BATCH*SEQ/128, 128>>>();
    out_kernel<<<dim3(FP/128, SEQ/128, BATCH), 256>>>();
    unpack_kernel<<<NMAT, 256>>>(out);
}

// round 15
// speedup vs baseline: 1.1250x; 1.1250x over previous
#include <cuda_runtime.h>
#include <math.h>

#define BATCH 16
#define SEQ   512
#define NDIM  32
#define NMAT  (BATCH*SEQ)     // 8192
#define FDIM  (NDIM*NDIM)     // 1024
#define FP    512             // padded packed feature dim
#define KEFF  496             // non-zero packed features

typedef unsigned long long u64;

// ---- packed f32x2 helpers ---------------------------------------------------
__device__ __forceinline__ u64 pack2(float lo, float hi) {
    u64 r; asm("mov.b64 %0, {%1, %2};" : "=l"(r) : "f"(lo), "f"(hi)); return r;
}
__device__ __forceinline__ u64 dup2(float v) {
    u64 r; asm("mov.b64 %0, {%1, %1};" : "=l"(r) : "f"(v)); return r;
}
__device__ __forceinline__ float2 unpack2(u64 v) {
    float2 f; asm("mov.b64 {%0, %1}, %2;" : "=f"(f.x), "=f"(f.y) : "l"(v)); return f;
}
#define FFMA2(acc, a2, b2) asm("fma.rn.f32x2 %0, %1, %2, %0;" : "+l"(acc) : "l"(a2), "l"(b2))
#define FMUL2I(g, s2)      asm("mul.rn.f32x2 %0, %0, %1;"     : "+l"(g)   : "l"(s2))
#define FADD2(d, a, b)     asm("add.rn.f32x2 %0, %1, %2;"     : "=l"(d)   : "l"(a), "l"(b))

// ---------------- scratch (static __device__, zero-initialized) ---------------
__device__ float d_qp[NMAT*FP];            // packed sqrt(2)*q lower-tri (pad 0)
__device__ float d_kp[NMAT*FP];            // packed sqrt(2)*k lower-tri (pad 0)
__device__ float d_vp[NMAT*FP];            // packed v lower-tri (pad 0)
__device__ float d_outp[NMAT*FP];          // packed output
__device__ float d_sc[BATCH*SEQ*SEQ];      // exp(scores)
__device__ float d_part[4*BATCH*SEQ];      // per-rowtile partial colsums
__device__ float d_isum[BATCH*SEQ];        // 1/colsum of exp
__device__ float d_C [3*FDIM];             // cayley matrices for q,k,v
__device__ float d_q2[NMAT];
__device__ float d_k2[NMAT];
__device__ volatile int d_cflag;           // cayley-done flag (benign replay race)

// ---------------- Cayley (one warp, one weight): C = (I-X)(I+X)^-1 ------------
__device__ void cayley_one(const float* __restrict__ W, float* __restrict__ Cout,
                           float (*Aug)[65], int lane) {
    for (int r = 0; r < 32; r++) {
        float xv = W[r*32 + lane] - W[lane*32 + r];
        float id = (r == lane) ? 1.f : 0.f;
        Aug[r][lane]      = id - xv;
        Aug[r][32 + lane] = id + xv;
    }
    __syncwarp();
    for (int kp = 0; kp < 32; kp++) {
        float ip = 1.f / Aug[kp][kp];
        __syncwarp();
        Aug[kp][lane]      *= ip;
        Aug[kp][32 + lane] *= ip;
        __syncwarp();
        for (int r = 0; r < 32; r++) {
            if (r == kp) continue;
            float f = Aug[r][kp];
            Aug[r][lane]      = fmaf(-f, Aug[kp][lane],      Aug[r][lane]);
            Aug[r][32 + lane] = fmaf(-f, Aug[kp][32 + lane], Aug[r][32 + lane]);
        }
        __syncwarp();
    }
    for (int i = 0; i < 32; i++)
        Cout[i*32 + lane] = Aug[lane][32 + i];
}

// ---------------- fused cayley + jacobi logm + transform ----------------------
// Block 0: 3 warps compute d_C, set flag. Blocks 1..NMAT/4: 4 warps, one
// 32x32 SPD matrix each: jacobi -> xl column in regs -> y_w packed.
#define CSTR 36
#define GT_OFF  0
#define AL_OFF  (4*32*17*8)            // 17408
#define CT_OFF  (AL_OFF + 4*32*4)      // 17920
#define SRAW_SZ (CT_OFF + 3*32*CSTR*4) // 31744 (cayley Aug 24960 fits too)
__global__ void __launch_bounds__(128, 5) jacobi_transform_kernel(
        const float* __restrict__ x,
        const float* __restrict__ qw, const float* __restrict__ kw,
        const float* __restrict__ vw) {
    __shared__ __align__(16) unsigned char sraw[SRAW_SZ];
    const int lane = threadIdx.x & 31;
    const int wip  = threadIdx.x >> 5;
    const unsigned FULL = 0xffffffffu;

    if (blockIdx.x == 0) {               // cayley block (first wave, ~6us)
        if (wip < 3) {
            float (*Aug)[65] = (float(*)[65])(sraw + wip * (32*65*4));
            const float* W = (wip == 0) ? qw : (wip == 1) ? kw : vw;
            cayley_one(W, d_C + wip*FDIM, Aug, lane);
        }
        __syncthreads();
        __threadfence();
        if (threadIdx.x == 0) d_cflag = 1;
        return;
    }

    u64  (*GT)[32][17] = (u64(*)[32][17])(sraw + GT_OFF);
    float (*Al)[32]    = (float(*)[32])(sraw + AL_OFF);
    float (*Ct)[32][CSTR] = (float(*)[32][CSTR])(sraw + CT_OFF);

    const int m = (blockIdx.x - 1) * 4 + wip;
    const float* A = x + (size_t)m * FDIM;

    u64 g2[16];
#pragma unroll
    for (int r = 0; r < 16; r++)
        g2[r] = pack2(A[(2*r)*32 + lane], A[(2*r+1)*32 + lane]);

    float nrm;
    {
        u64 nA = 0ull, nB = 0ull, nC = 0ull, nD = 0ull;
#pragma unroll
        for (int r = 0; r < 4; r++) {
            FFMA2(nA, g2[r],      g2[r]);
            FFMA2(nB, g2[4 + r],  g2[4 + r]);
            FFMA2(nC, g2[8 + r],  g2[8 + r]);
            FFMA2(nD, g2[12 + r], g2[12 + r]);
        }
        u64 s; FADD2(s, nA, nB); u64 t2; FADD2(t2, nC, nD); FADD2(s, s, t2);
        float2 nf = unpack2(s);
        nrm = nf.x + nf.y;
    }
    float scale = 1.f, iscale = 1.f;

    for (int sweep = 0; sweep < 6; sweep++) {
        bool big = false;
        for (int mm = 1; mm < 32; mm++) {
            const int partner = lane ^ mm;
            u64 h2[16];
#pragma unroll
            for (int r = 0; r < 16; r++) h2[r] = __shfl_xor_sync(FULL, g2[r], mm);
            u64 dA = 0ull, dB = 0ull, dC = 0ull, dD = 0ull;
#pragma unroll
            for (int r = 0; r < 4; r++) {
                FFMA2(dA, g2[r],      h2[r]);
                FFMA2(dB, g2[4 + r],  h2[4 + r]);
                FFMA2(dC, g2[8 + r],  h2[8 + r]);
                FFMA2(dD, g2[12 + r], h2[12 + r]);
            }
            u64 ds; FADD2(ds, dA, dB); u64 dt; FADD2(dt, dC, dD); FADD2(ds, ds, dt);
            float2 df = unpack2(ds);
            float dotv = df.x + df.y;
            float nrm_o = __shfl_xor_sync(FULL, nrm,   mm);
            float sc_o  = __shfl_xor_sync(FULL, scale, mm);
            float apq = dotv * scale * sc_o;
            const bool is_p = lane < partner;
            float app = is_p ? nrm : nrm_o;
            float aqq = is_p ? nrm_o : nrm;
            float prod = app * aqq;
            float c2v  = apq * apq;
            big = big || (c2v > 1e-4f * prod);
            bool rot = (c2v > 1e-8f * prod);
            unsigned ball = __ballot_sync(FULL, rot);
            if (ball) {
                if (rot) {
                    float tau = (aqq - app) * 0.5f / apq;
                    float t   = copysignf(1.f, tau) / (fabsf(tau) + sqrtf(fmaf(tau, tau, 1.f)));
                    float u   = fmaf(t, t, 1.f);
                    float cc  = rsqrtf(u);
                    float rc  = sqrtf(u);
                    float spt = is_p ? -t : t;
                    u64 c2 = dup2(spt * sc_o * iscale);
#pragma unroll
                    for (int r = 0; r < 16; r++) FFMA2(g2[r], c2, h2[r]);
                    nrm = fmaf(spt, apq, nrm);
                    scale *= cc; iscale *= rc;
                }
            }
        }
        u64 s2 = dup2(scale);
#pragma unroll
        for (int r = 0; r < 16; r++) FMUL2I(g2[r], s2);
        scale = 1.f; iscale = 1.f;
        if (!__any_sync(FULL, big)) break;
    }

    float nx;
    {
        u64 nA = 0ull, nB = 0ull, nC = 0ull, nD = 0ull;
#pragma unroll
        for (int r = 0; r < 4; r++) {
            FFMA2(nA, g2[r],      g2[r]);
            FFMA2(nB, g2[4 + r],  g2[4 + r]);
            FFMA2(nC, g2[8 + r],  g2[8 + r]);
            FFMA2(nD, g2[12 + r], g2[12 + r]);
        }
        u64 s; FADD2(s, nA, nB); u64 t2; FADD2(t2, nC, nD); FADD2(s, s, t2);
        float2 xf = unpack2(s);
        nx = xf.x + xf.y;
    }
    float alpha = 0.5f * logf(nx) / nx;

    // ---- rank-1 reconstruction via packed u64 shared columns ----
    u64* myG = &GT[wip][lane][0];
#pragma unroll
    for (int r = 0; r < 16; r++) myG[r] = g2[r];
    Al[wip][lane] = alpha;
    __syncwarp();

    u64 acc[16];
#pragma unroll
    for (int r = 0; r < 16; r++) acc[r] = 0ull;
#pragma unroll 4
    for (int t = 0; t < 32; t++) {
        const u64* col = &GT[wip][t][0];
        float2 gf = unpack2(col[lane >> 1]);
        float gelem = (lane & 1) ? gf.y : gf.x;
        u64 coef = dup2(Al[wip][t] * gelem);
#pragma unroll
        for (int r = 0; r < 16; r++) {
            u64 cv = col[r];
            FFMA2(acc[r], coef, cv);
        }
    }
    {
        float2 e = unpack2(acc[lane >> 1]);
        if (lane & 1) e.y = 0.f; else e.x = 0.f;
        acc[lane >> 1] = pack2(e.x, e.y);
    }

    // ---- wait for cayley, then cooperative Ct load --------------------------
    if (threadIdx.x == 0) { while (d_cflag == 0) { } }
    __syncthreads();          // all lanes past GT reads + flag observed
    __threadfence();
    for (int idx = threadIdx.x; idx < 3*1024; idx += 128) {
        int w = idx >> 10, rem = idx & 1023, i = rem >> 5, k = rem & 31;
        Ct[w][k][i] = d_C[w*FDIM + i*32 + k];
    }
    __syncthreads();

    // ---- transform phase: y_w = C_w * X * C_w^T, X columns in acc ----
    for (int w = 0; w < 3; w++) {
        u64 accT[16];
#pragma unroll
        for (int r = 0; r < 16; r++) accT[r] = 0ull;
#pragma unroll
        for (int k = 0; k < 32; k++) {
            float2 xe = unpack2(acc[k >> 1]);
            u64 c2 = dup2((k & 1) ? xe.y : xe.x);
            const ulonglong2* crow = (const ulonglong2*)&Ct[w][k][0];
#pragma unroll
            for (int p = 0; p < 8; p++) {
                ulonglong2 cv = crow[p];
                FFMA2(accT[2*p],   c2, cv.x);
                FFMA2(accT[2*p+1], c2, cv.y);
            }
        }
        __syncwarp();
#pragma unroll
        for (int r = 0; r < 16; r++) GT[wip][lane][r] = accT[r];
        __syncwarp();

        u64 acy[16];
#pragma unroll
        for (int r = 0; r < 16; r++) acy[r] = 0ull;
#pragma unroll
        for (int k = 0; k < 32; k++) {
            u64 c2 = dup2(Ct[w][k][lane]);
#pragma unroll
            for (int r = 0; r < 16; r++) {
                u64 tv = GT[wip][k][r];
                FFMA2(acy[r], c2, tv);
            }
        }

        float y[32];
#pragma unroll
        for (int r = 0; r < 16; r++) {
            float2 t = unpack2(acy[r]);
            y[2*r] = t.x; y[2*r+1] = t.y;
        }
        float* dst = (w == 0) ? d_qp : (w == 1) ? d_kp : d_vp;
        const float fac = (w < 2) ? 1.41421356237f : 1.f;
        float s = 0.f;
#pragma unroll
        for (int i = 1; i < 32; i++) {
            if (lane < i) {
                float yv = y[i];
                dst[(size_t)m*FP + i*(i-1)/2 + lane] = fac * yv;
                s = fmaf(yv, yv, s);
            }
        }
        if (w < 2) {
#pragma unroll
            for (int off = 16; off; off >>= 1) s += __shfl_down_sync(0xffffffffu, s, off);
            if (lane == 0) { if (w == 0) d_q2[m] = 2.f*s; else d_k2[m] = 2.f*s; }
        }
        __syncwarp();
    }
}

// ---------------- scores GEMM 128x128xK(496 packed), f32x2, fused colsum -----
__global__ void __launch_bounds__(256, 2) scores_kernel() {
    const int b  = blockIdx.z;
    const int mt = blockIdx.y * 128;
    const int nt = blockIdx.x * 128;
    const float* Ab = d_kp + (size_t)b * SEQ * FP;
    const float* Bb = d_qp + (size_t)b * SEQ * FP;
    __shared__ __align__(16) float As[2][16][132];
    __shared__ __align__(16) float Bs[2][16][132];
    __shared__ float Ssum[16][128];
    const int tid = threadIdx.x;
    const int lr = tid >> 2, lc = (tid & 3) << 2;
    const int tx = tid & 15, ty = tid >> 4;
    const int m0 = ty << 3;
    const int nA = tx << 2;
    const int nB = 64 + (tx << 2);

    u64 acc2[8][4];
#pragma unroll
    for (int ii = 0; ii < 8; ii++)
#pragma unroll
        for (int p = 0; p < 4; p++) acc2[ii][p] = 0ull;

    const float* ap0 = Ab + (size_t)(mt + lr) * FP + lc;
    const float* ap1 = ap0 + (size_t)64 * FP;
    const float* bp0 = Bb + (size_t)(nt + lr) * FP + lc;
    const float* bp1 = bp0 + (size_t)64 * FP;

    {
        float4 a0 = *(const float4*)ap0, a1 = *(const float4*)ap1;
        float4 b0 = *(const float4*)bp0, b1 = *(const float4*)bp1;
        As[0][lc+0][lr]=a0.x; As[0][lc+1][lr]=a0.y; As[0][lc+2][lr]=a0.z; As[0][lc+3][lr]=a0.w;
        As[0][lc+0][lr+64]=a1.x; As[0][lc+1][lr+64]=a1.y; As[0][lc+2][lr+64]=a1.z; As[0][lc+3][lr+64]=a1.w;
        Bs[0][lc+0][lr]=b0.x; Bs[0][lc+1][lr]=b0.y; Bs[0][lc+2][lr]=b0.z; Bs[0][lc+3][lr]=b0.w;
        Bs[0][lc+0][lr+64]=b1.x; Bs[0][lc+1][lr+64]=b1.y; Bs[0][lc+2][lr+64]=b1.z; Bs[0][lc+3][lr+64]=b1.w;
    }
    __syncthreads();

    int buf = 0;
#pragma unroll 1
    for (int kt = 0; kt < KEFF; kt += 16) {
        float4 na0, na1, nb0, nb1;
        const bool more = (kt + 16 < KEFF);
        if (more) {
            na0 = *(const float4*)(ap0 + kt + 16);
            na1 = *(const float4*)(ap1 + kt + 16);
            nb0 = *(const float4*)(bp0 + kt + 16);
            nb1 = *(const float4*)(bp1 + kt + 16);
        }
#pragma unroll
        for (int kk = 0; kk < 16; kk++) {
            float a[8];
            *(float4*)(a)     = *(const float4*)&As[buf][kk][m0];
            *(float4*)(a + 4) = *(const float4*)&As[buf][kk][m0 + 4];
            ulonglong2 bu0 = *(const ulonglong2*)&Bs[buf][kk][nA];
            ulonglong2 bu1 = *(const ulonglong2*)&Bs[buf][kk][nB];
#pragma unroll
            for (int ii = 0; ii < 8; ii++) {
                u64 a2 = dup2(a[ii]);
                FFMA2(acc2[ii][0], a2, bu0.x);
                FFMA2(acc2[ii][1], a2, bu0.y);
                FFMA2(acc2[ii][2], a2, bu1.x);
                FFMA2(acc2[ii][3], a2, bu1.y);
            }
        }
        if (more) {
            const int nb = buf ^ 1;
            As[nb][lc+0][lr]=na0.x; As[nb][lc+1][lr]=na0.y; As[nb][lc+2][lr]=na0.z; As[nb][lc+3][lr]=na0.w;
            As[nb][lc+0][lr+64]=na1.x; As[nb][lc+1][lr+64]=na1.y; As[nb][lc+2][lr+64]=na1.z; As[nb][lc+3][lr+64]=na1.w;
            Bs[nb][lc+0][lr]=nb0.x; Bs[nb][lc+1][lr]=nb0.y; Bs[nb][lc+2][lr]=nb0.z; Bs[nb][lc+3][lr]=nb0.w;
            Bs[nb][lc+0][lr+64]=nb1.x; Bs[nb][lc+1][lr+64]=nb1.y; Bs[nb][lc+2][lr+64]=nb1.z; Bs[nb][lc+3][lr+64]=nb1.w;
        }
        __syncthreads();
        buf ^= 1;
    }

    float q2c[8];
#pragma unroll
    for (int jj = 0; jj < 4; jj++) q2c[jj]     = d_q2[b*SEQ + nt + nA + jj];
#pragma unroll
    for (int jj = 0; jj < 4; jj++) q2c[4 + jj] = d_q2[b*SEQ + nt + nB + jj];
    float csum[8];
#pragma unroll
    for (int jj = 0; jj < 8; jj++) csum[jj] = 0.f;
#pragma unroll
    for (int ii = 0; ii < 8; ii++) {
        float k2r = d_k2[b*SEQ + mt + m0 + ii];
        float o[8];
#pragma unroll
        for (int p = 0; p < 4; p++) {
            float2 ab = unpack2(acc2[ii][p]);
            float d2a = fmaxf(k2r + q2c[2*p]   - 2.f * ab.x, 1e-12f);
            float d2b = fmaxf(k2r + q2c[2*p+1] - 2.f * ab.y, 1e-12f);
            o[2*p]   = __expf(1.f / (1.f + __logf(1.f + sqrtf(d2a))));
            o[2*p+1] = __expf(1.f / (1.f + __logf(1.f + sqrtf(d2b))));
        }
#pragma unroll
        for (int jj = 0; jj < 8; jj++) csum[jj] += o[jj];
        float* row = d_sc + ((size_t)b*SEQ + mt + m0 + ii)*SEQ + nt;
        *(float4*)(row + nA) = make_float4(o[0], o[1], o[2], o[3]);
        *(float4*)(row + nB) = make_float4(o[4], o[5], o[6], o[7]);
    }
    *(float4*)&Ssum[ty][nA] = make_float4(csum[0], csum[1], csum[2], csum[3]);
    *(float4*)&Ssum[ty][nB] = make_float4(csum[4], csum[5], csum[6], csum[7]);
    __syncthreads();
    if (tid < 128) {
        float s = 0.f;
#pragma unroll
        for (int t = 0; t < 16; t++) s += Ssum[t][tid];
        d_part[(blockIdx.y * BATCH + b) * SEQ + nt + tid] = s;
    }
}

// ---------------- finalize colsum: 1/sum of 4 partials -----------------------
__global__ void softsum2_kernel() {
    const int i = blockIdx.x * 256 + threadIdx.x;
    float s = d_part[i] + d_part[BATCH*SEQ + i]
            + d_part[2*BATCH*SEQ + i] + d_part[3*BATCH*SEQ + i];
    d_isum[i] = 1.f / s;
}

// ---------------- out GEMM 128x128x16 over packed N=512, f32x2 ---------------
__global__ void __launch_bounds__(256) out_kernel() {
    const int b  = blockIdx.z;
    const int mt = blockIdx.y * 128;
    const int nt = blockIdx.x * 128;
    const float* Ab = d_sc + (size_t)b * SEQ * SEQ;
    const float* Bb = d_vp + (size_t)b * SEQ * FP;
    const float* isum = d_isum + b * SEQ;
    __shared__ __align__(16) float As[2][16][132];
    __shared__ __align__(16) float Bs[2][16][132];
    const int tid = threadIdx.x;
    const int lr = tid >> 2, lc = (tid & 3) << 2;
    const int br = tid >> 5, bc = (tid & 31) << 2;
    const int tx = tid & 15, ty = tid >> 4;
    const int m0 = ty << 3;
    const int nA = tx << 2;
    const int nB = 64 + (tx << 2);

    u64 acc2[8][4];
#pragma unroll
    for (int ii = 0; ii < 8; ii++)
#pragma unroll
        for (int p = 0; p < 4; p++) acc2[ii][p] = 0ull;

    const float* ap0 = Ab + (size_t)(mt + lr) * SEQ + lc;
    const float* ap1 = ap0 + (size_t)64 * SEQ;
    const float* bq0 = Bb + (size_t)br * FP + nt + bc;
    const float* bq1 = bq0 + (size_t)8 * FP;

    {
        float4 a0 = *(const float4*)ap0, a1 = *(const float4*)ap1;
        float4 v0 = *(const float4*)bq0, v1 = *(const float4*)bq1;
        float s0 = isum[br], s1 = isum[br + 8];
        As[0][lc+0][lr]=a0.x; As[0][lc+1][lr]=a0.y; As[0][lc+2][lr]=a0.z; As[0][lc+3][lr]=a0.w;
        As[0][lc+0][lr+64]=a1.x; As[0][lc+1][lr+64]=a1.y; As[0][lc+2][lr+64]=a1.z; As[0][lc+3][lr+64]=a1.w;
        *(float4*)&Bs[0][br][bc]   = make_float4(v0.x*s0, v0.y*s0, v0.z*s0, v0.w*s0);
        *(float4*)&Bs[0][br+8][bc] = make_float4(v1.x*s1, v1.y*s1, v1.z*s1, v1.w*s1);
    }
    __syncthreads();

    int buf = 0;
#pragma unroll 1
    for (int kt = 0; kt < SEQ; kt += 16) {
        float4 na0, na1, nv0, nv1;
        float s0 = 0.f, s1 = 0.f;
        const bool more = (kt + 16 < SEQ);
        if (more) {
            na0 = *(const float4*)(ap0 + kt + 16);
            na1 = *(const float4*)(ap1 + kt + 16);
            nv0 = *(const float4*)(bq0 + (size_t)(kt + 16) * FP);
            nv1 = *(const float4*)(bq1 + (size_t)(kt + 16) * FP);
            s0 = isum[kt + 16 + br];
            s1 = isum[kt + 16 + br + 8];
        }
#pragma unroll
        for (int kk = 0; kk < 16; kk++) {
            float a[8];
            *(float4*)(a)     = *(const float4*)&As[buf][kk][m0];
            *(float4*)(a + 4) = *(const float4*)&As[buf][kk][m0 + 4];
            ulonglong2 bu0 = *(const ulonglong2*)&Bs[buf][kk][nA];
            ulonglong2 bu1 = *(const ulonglong2*)&Bs[buf][kk][nB];
#pragma unroll
            for (int ii = 0; ii < 8; ii++) {
                u64 a2 = dup2(a[ii]);
                FFMA2(acc2[ii][0], a2, bu0.x);
                FFMA2(acc2[ii][1], a2, bu0.y);
                FFMA2(acc2[ii][2], a2, bu1.x);
                FFMA2(acc2[ii][3], a2, bu1.y);
            }
        }
        if (more) {
            const int nb = buf ^ 1;
            As[nb][lc+0][lr]=na0.x; As[nb][lc+1][lr]=na0.y; As[nb][lc+2][lr]=na0.z; As[nb][lc+3][lr]=na0.w;
            As[nb][lc+0][lr+64]=na1.x; As[nb][lc+1][lr+64]=na1.y; As[nb][lc+2][lr+64]=na1.z; As[nb][lc+3][lr+64]=na1.w;
            *(float4*)&Bs[nb][br][bc]   = make_float4(nv0.x*s0, nv0.y*s0, nv0.z*s0, nv0.w*s0);
            *(float4*)&Bs[nb][br+8][bc] = make_float4(nv1.x*s1, nv1.y*s1, nv1.z*s1, nv1.w*s1);
        }
        __syncthreads();
        buf ^= 1;
    }

#pragma unroll
    for (int ii = 0; ii < 8; ii++) {
        float* dst = d_outp + ((size_t)b*SEQ + mt + m0 + ii)*FP + nt;
        ulonglong2 s0; s0.x = acc2[ii][0]; s0.y = acc2[ii][1];
        ulonglong2 s1; s1.x = acc2[ii][2]; s1.y = acc2[ii][3];
        *(ulonglong2*)(dst + nA) = s0;
        *(ulonglong2*)(dst + nB) = s1;
    }
}

// ---------------- unpack: packed 496 -> full symmetric 32x32, diag 0 ---------
__global__ void __launch_bounds__(256) unpack_kernel(float* __restrict__ out) {
    const int m = blockIdx.x;
    const float* src = d_outp + (size_t)m * FP;
    float* dst = out + (size_t)m * FDIM;
#pragma unroll
    for (int e = 0; e < 4; e++) {
        const int idx = threadIdx.x + e * 256;
        const int i = idx >> 5, j = idx & 31;
        float v = 0.f;
        if (i != j) {
            const int hi = (i > j) ? i : j;
            const int lo = (i > j) ? j : i;
            v = src[hi*(hi-1)/2 + lo];
        }
        dst[idx] = v;
    }
}

// ---------------- launch ----------------------------------------------------
extern "C" void kernel_launch(void* const* d_in, const int* in_sizes, int n_in,
                              void* d_out, int out_size) {
    (void)in_sizes; (void)n_in; (void)out_size;
    const float* x  = (const float*)d_in[0];
    const float* qw = (const float*)d_in[1];
    const float* kw = (const float*)d_in[2];
    const float* vw = (const float*)d_in[3];
    float* out = (float*)d_out;

    jacobi_transform_kernel<<<NMAT/4 + 1, 128>>>(x, qw, kw, vw);
    scores_kernel<<<dim3(SEQ/128, SEQ/128, BATCH), 256>>>();
    softsum2_kernel<<<BATCH*SEQ/256, 256>>>();
    out_kernel<<<dim3(FP/128, SEQ/128, BATCH), 256>>>();
    unpack_kernel<<<NMAT, 256>>>(out);
}

// round 16
// speedup vs baseline: 1.1774x; 1.0466x over previous
#include <cuda_runtime.h>
#include <math.h>

#define BATCH 16
#define SEQ   512
#define NDIM  32
#define NMAT  (BATCH*SEQ)     // 8192
#define FDIM  (NDIM*NDIM)     // 1024
#define FP    512             // padded packed feature dim
#define KEFF  496             // non-zero packed features

typedef unsigned long long u64;

// ---- packed f32x2 helpers ---------------------------------------------------
__device__ __forceinline__ u64 pack2(float lo, float hi) {
    u64 r; asm("mov.b64 %0, {%1, %2};" : "=l"(r) : "f"(lo), "f"(hi)); return r;
}
__device__ __forceinline__ u64 dup2(float v) {
    u64 r; asm("mov.b64 %0, {%1, %1};" : "=l"(r) : "f"(v)); return r;
}
__device__ __forceinline__ float2 unpack2(u64 v) {
    float2 f; asm("mov.b64 {%0, %1}, %2;" : "=f"(f.x), "=f"(f.y) : "l"(v)); return f;
}
#define FFMA2(acc, a2, b2) asm("fma.rn.f32x2 %0, %1, %2, %0;" : "+l"(acc) : "l"(a2), "l"(b2))
#define FMUL2I(g, s2)      asm("mul.rn.f32x2 %0, %0, %1;"     : "+l"(g)   : "l"(s2))
#define FADD2(d, a, b)     asm("add.rn.f32x2 %0, %1, %2;"     : "=l"(d)   : "l"(a), "l"(b))

// ---------------- scratch (static __device__, zero-initialized) ---------------
__device__ float d_qp[NMAT*FP];            // packed sqrt(2)*q lower-tri (pad 0)
__device__ float d_kp[NMAT*FP];            // packed sqrt(2)*k lower-tri (pad 0)
__device__ float d_vp[NMAT*FP];            // packed v lower-tri (pad 0)
__device__ float d_outp[NMAT*FP];          // packed output
__device__ float d_sc[BATCH*SEQ*SEQ];      // exp(scores)
__device__ float d_part[4*BATCH*SEQ];      // per-rowtile partial colsums
__device__ float d_isum[BATCH*SEQ];        // 1/colsum of exp
__device__ float d_C [3*FDIM];             // cayley matrices for q,k,v
__device__ float d_q2[NMAT];
__device__ float d_k2[NMAT];
__device__ volatile int d_cflag;           // cayley-done flag (benign replay race)

// ---------------- Cayley (one warp, one weight): C = (I-X)(I+X)^-1 ------------
__device__ void cayley_one(const float* __restrict__ W, float* __restrict__ Cout,
                           float (*Aug)[65], int lane) {
    for (int r = 0; r < 32; r++) {
        float xv = W[r*32 + lane] - W[lane*32 + r];
        float id = (r == lane) ? 1.f : 0.f;
        Aug[r][lane]      = id - xv;
        Aug[r][32 + lane] = id + xv;
    }
    __syncwarp();
    for (int kp = 0; kp < 32; kp++) {
        float ip = 1.f / Aug[kp][kp];
        __syncwarp();
        Aug[kp][lane]      *= ip;
        Aug[kp][32 + lane] *= ip;
        __syncwarp();
        for (int r = 0; r < 32; r++) {
            if (r == kp) continue;
            float f = Aug[r][kp];
            Aug[r][lane]      = fmaf(-f, Aug[kp][lane],      Aug[r][lane]);
            Aug[r][32 + lane] = fmaf(-f, Aug[kp][32 + lane], Aug[r][32 + lane]);
        }
        __syncwarp();
    }
    for (int i = 0; i < 32; i++)
        Cout[i*32 + lane] = Aug[lane][32 + i];
}

// ---------------- fused cayley + jacobi logm + transform ----------------------
#define CSTR 36
#define GT_OFF  0
#define AL_OFF  (4*32*17*8)            // 17408
#define CT_OFF  (AL_OFF + 4*32*4)      // 17920
#define SRAW_SZ (CT_OFF + 3*32*CSTR*4) // 31744
__global__ void __launch_bounds__(128, 5) jacobi_transform_kernel(
        const float* __restrict__ x,
        const float* __restrict__ qw, const float* __restrict__ kw,
        const float* __restrict__ vw) {
    __shared__ __align__(16) unsigned char sraw[SRAW_SZ];
    const int lane = threadIdx.x & 31;
    const int wip  = threadIdx.x >> 5;
    const unsigned FULL = 0xffffffffu;

    if (blockIdx.x == 0) {               // cayley block (first wave)
        if (wip < 3) {
            float (*Aug)[65] = (float(*)[65])(sraw + wip * (32*65*4));
            const float* W = (wip == 0) ? qw : (wip == 1) ? kw : vw;
            cayley_one(W, d_C + wip*FDIM, Aug, lane);
        }
        __syncthreads();
        __threadfence();
        if (threadIdx.x == 0) d_cflag = 1;
        return;
    }

    u64  (*GT)[32][17] = (u64(*)[32][17])(sraw + GT_OFF);
    float (*Al)[32]    = (float(*)[32])(sraw + AL_OFF);
    float (*Ct)[32][CSTR] = (float(*)[32][CSTR])(sraw + CT_OFF);

    const int m = (blockIdx.x - 1) * 4 + wip;
    const float* A = x + (size_t)m * FDIM;

    u64 g2[16];
#pragma unroll
    for (int r = 0; r < 16; r++)
        g2[r] = pack2(A[(2*r)*32 + lane], A[(2*r+1)*32 + lane]);

    float nrm;
    {
        u64 nA = 0ull, nB = 0ull, nC = 0ull, nD = 0ull;
#pragma unroll
        for (int r = 0; r < 4; r++) {
            FFMA2(nA, g2[r],      g2[r]);
            FFMA2(nB, g2[4 + r],  g2[4 + r]);
            FFMA2(nC, g2[8 + r],  g2[8 + r]);
            FFMA2(nD, g2[12 + r], g2[12 + r]);
        }
        u64 s; FADD2(s, nA, nB); u64 t2; FADD2(t2, nC, nD); FADD2(s, s, t2);
        float2 nf = unpack2(s);
        nrm = nf.x + nf.y;
    }
    float scale = 1.f, iscale = 1.f;

    for (int sweep = 0; sweep < 6; sweep++) {
        bool big = false;
        for (int mm = 1; mm < 32; mm++) {
            const int partner = lane ^ mm;
            u64 h2[16];
#pragma unroll
            for (int r = 0; r < 16; r++) h2[r] = __shfl_xor_sync(FULL, g2[r], mm);
            u64 dA = 0ull, dB = 0ull, dC = 0ull, dD = 0ull;
#pragma unroll
            for (int r = 0; r < 4; r++) {
                FFMA2(dA, g2[r],      h2[r]);
                FFMA2(dB, g2[4 + r],  h2[4 + r]);
                FFMA2(dC, g2[8 + r],  h2[8 + r]);
                FFMA2(dD, g2[12 + r], h2[12 + r]);
            }
            u64 ds; FADD2(ds, dA, dB); u64 dt; FADD2(dt, dC, dD); FADD2(ds, ds, dt);
            float2 df = unpack2(ds);
            float dotv = df.x + df.y;
            float nrm_o = __shfl_xor_sync(FULL, nrm,   mm);
            float sc_o  = __shfl_xor_sync(FULL, scale, mm);
            float apq = dotv * scale * sc_o;
            const bool is_p = lane < partner;
            float app = is_p ? nrm : nrm_o;
            float aqq = is_p ? nrm_o : nrm;
            float prod = app * aqq;
            float c2v  = apq * apq;
            big = big || (c2v > 1e-4f * prod);
            bool rot = (c2v > 1e-8f * prod);
            unsigned ball = __ballot_sync(FULL, rot);
            if (ball) {
                if (rot) {
                    float tau = (aqq - app) * 0.5f / apq;
                    float t   = copysignf(1.f, tau) / (fabsf(tau) + sqrtf(fmaf(tau, tau, 1.f)));
                    float u   = fmaf(t, t, 1.f);
                    float cc  = rsqrtf(u);
                    float rc  = sqrtf(u);
                    float spt = is_p ? -t : t;
                    u64 c2 = dup2(spt * sc_o * iscale);
#pragma unroll
                    for (int r = 0; r < 16; r++) FFMA2(g2[r], c2, h2[r]);
                    nrm = fmaf(spt, apq, nrm);
                    scale *= cc; iscale *= rc;
                }
            }
        }
        u64 s2 = dup2(scale);
#pragma unroll
        for (int r = 0; r < 16; r++) FMUL2I(g2[r], s2);
        scale = 1.f; iscale = 1.f;
        if (!__any_sync(FULL, big)) break;
    }

    float nx;
    {
        u64 nA = 0ull, nB = 0ull, nC = 0ull, nD = 0ull;
#pragma unroll
        for (int r = 0; r < 4; r++) {
            FFMA2(nA, g2[r],      g2[r]);
            FFMA2(nB, g2[4 + r],  g2[4 + r]);
            FFMA2(nC, g2[8 + r],  g2[8 + r]);
            FFMA2(nD, g2[12 + r], g2[12 + r]);
        }
        u64 s; FADD2(s, nA, nB); u64 t2; FADD2(t2, nC, nD); FADD2(s, s, t2);
        float2 xf = unpack2(s);
        nx = xf.x + xf.y;
    }
    float alpha = 0.5f * logf(nx) / nx;

    u64* myG = &GT[wip][lane][0];
#pragma unroll
    for (int r = 0; r < 16; r++) myG[r] = g2[r];
    Al[wip][lane] = alpha;
    __syncwarp();

    u64 acc[16];
#pragma unroll
    for (int r = 0; r < 16; r++) acc[r] = 0ull;
#pragma unroll 4
    for (int t = 0; t < 32; t++) {
        const u64* col = &GT[wip][t][0];
        float2 gf = unpack2(col[lane >> 1]);
        float gelem = (lane & 1) ? gf.y : gf.x;
        u64 coef = dup2(Al[wip][t] * gelem);
#pragma unroll
        for (int r = 0; r < 16; r++) {
            u64 cv = col[r];
            FFMA2(acc[r], coef, cv);
        }
    }
    {
        float2 e = unpack2(acc[lane >> 1]);
        if (lane & 1) e.y = 0.f; else e.x = 0.f;
        acc[lane >> 1] = pack2(e.x, e.y);
    }

    if (threadIdx.x == 0) { while (d_cflag == 0) { } }
    __syncthreads();
    __threadfence();
    for (int idx = threadIdx.x; idx < 3*1024; idx += 128) {
        int w = idx >> 10, rem = idx & 1023, i = rem >> 5, k = rem & 31;
        Ct[w][k][i] = d_C[w*FDIM + i*32 + k];
    }
    __syncthreads();

    for (int w = 0; w < 3; w++) {
        u64 accT[16];
#pragma unroll
        for (int r = 0; r < 16; r++) accT[r] = 0ull;
#pragma unroll
        for (int k = 0; k < 32; k++) {
            float2 xe = unpack2(acc[k >> 1]);
            u64 c2 = dup2((k & 1) ? xe.y : xe.x);
            const ulonglong2* crow = (const ulonglong2*)&Ct[w][k][0];
#pragma unroll
            for (int p = 0; p < 8; p++) {
                ulonglong2 cv = crow[p];
                FFMA2(accT[2*p],   c2, cv.x);
                FFMA2(accT[2*p+1], c2, cv.y);
            }
        }
        __syncwarp();
#pragma unroll
        for (int r = 0; r < 16; r++) GT[wip][lane][r] = accT[r];
        __syncwarp();

        u64 acy[16];
#pragma unroll
        for (int r = 0; r < 16; r++) acy[r] = 0ull;
#pragma unroll
        for (int k = 0; k < 32; k++) {
            u64 c2 = dup2(Ct[w][k][lane]);
#pragma unroll
            for (int r = 0; r < 16; r++) {
                u64 tv = GT[wip][k][r];
                FFMA2(acy[r], c2, tv);
            }
        }

        float y[32];
#pragma unroll
        for (int r = 0; r < 16; r++) {
            float2 t = unpack2(acy[r]);
            y[2*r] = t.x; y[2*r+1] = t.y;
        }
        float* dst = (w == 0) ? d_qp : (w == 1) ? d_kp : d_vp;
        const float fac = (w < 2) ? 1.41421356237f : 1.f;
        float s = 0.f;
#pragma unroll
        for (int i = 1; i < 32; i++) {
            if (lane < i) {
                float yv = y[i];
                dst[(size_t)m*FP + i*(i-1)/2 + lane] = fac * yv;
                s = fmaf(yv, yv, s);
            }
        }
        if (w < 2) {
#pragma unroll
            for (int off = 16; off; off >>= 1) s += __shfl_down_sync(0xffffffffu, s, off);
            if (lane == 0) { if (w == 0) d_q2[m] = 2.f*s; else d_k2[m] = 2.f*s; }
        }
        __syncwarp();
    }
}

// ---------------- scores GEMM 128x128xK(496 packed), f32x2, fused colsum -----
__global__ void __launch_bounds__(256, 2) scores_kernel() {
    const int b  = blockIdx.z;
    const int mt = blockIdx.y * 128;
    const int nt = blockIdx.x * 128;
    const float* Ab = d_kp + (size_t)b * SEQ * FP;
    const float* Bb = d_qp + (size_t)b * SEQ * FP;
    __shared__ __align__(16) float As[2][16][132];
    __shared__ __align__(16) float Bs[2][16][132];
    __shared__ float Ssum[16][128];
    const int tid = threadIdx.x;
    const int lr = tid >> 2, lc = (tid & 3) << 2;
    const int tx = tid & 15, ty = tid >> 4;
    const int m0 = ty << 3;
    const int nA = tx << 2;
    const int nB = 64 + (tx << 2);

    u64 acc2[8][4];
#pragma unroll
    for (int ii = 0; ii < 8; ii++)
#pragma unroll
        for (int p = 0; p < 4; p++) acc2[ii][p] = 0ull;

    const float* ap0 = Ab + (size_t)(mt + lr) * FP + lc;
    const float* ap1 = ap0 + (size_t)64 * FP;
    const float* bp0 = Bb + (size_t)(nt + lr) * FP + lc;
    const float* bp1 = bp0 + (size_t)64 * FP;

    {
        float4 a0 = *(const float4*)ap0, a1 = *(const float4*)ap1;
        float4 b0 = *(const float4*)bp0, b1 = *(const float4*)bp1;
        As[0][lc+0][lr]=a0.x; As[0][lc+1][lr]=a0.y; As[0][lc+2][lr]=a0.z; As[0][lc+3][lr]=a0.w;
        As[0][lc+0][lr+64]=a1.x; As[0][lc+1][lr+64]=a1.y; As[0][lc+2][lr+64]=a1.z; As[0][lc+3][lr+64]=a1.w;
        Bs[0][lc+0][lr]=b0.x; Bs[0][lc+1][lr]=b0.y; Bs[0][lc+2][lr]=b0.z; Bs[0][lc+3][lr]=b0.w;
        Bs[0][lc+0][lr+64]=b1.x; Bs[0][lc+1][lr+64]=b1.y; Bs[0][lc+2][lr+64]=b1.z; Bs[0][lc+3][lr+64]=b1.w;
    }
    __syncthreads();

    int buf = 0;
#pragma unroll 1
    for (int kt = 0; kt < KEFF; kt += 16) {
        float4 na0, na1, nb0, nb1;
        const bool more = (kt + 16 < KEFF);
        if (more) {
            na0 = *(const float4*)(ap0 + kt + 16);
            na1 = *(const float4*)(ap1 + kt + 16);
            nb0 = *(const float4*)(bp0 + kt + 16);
            nb1 = *(const float4*)(bp1 + kt + 16);
        }
#pragma unroll
        for (int kk = 0; kk < 16; kk++) {
            float a[8];
            *(float4*)(a)     = *(const float4*)&As[buf][kk][m0];
            *(float4*)(a + 4) = *(const float4*)&As[buf][kk][m0 + 4];
            ulonglong2 bu0 = *(const ulonglong2*)&Bs[buf][kk][nA];
            ulonglong2 bu1 = *(const ulonglong2*)&Bs[buf][kk][nB];
#pragma unroll
            for (int ii = 0; ii < 8; ii++) {
                u64 a2 = dup2(a[ii]);
                FFMA2(acc2[ii][0], a2, bu0.x);
                FFMA2(acc2[ii][1], a2, bu0.y);
                FFMA2(acc2[ii][2], a2, bu1.x);
                FFMA2(acc2[ii][3], a2, bu1.y);
            }
        }
        if (more) {
            const int nb = buf ^ 1;
            As[nb][lc+0][lr]=na0.x; As[nb][lc+1][lr]=na0.y; As[nb][lc+2][lr]=na0.z; As[nb][lc+3][lr]=na0.w;
            As[nb][lc+0][lr+64]=na1.x; As[nb][lc+1][lr+64]=na1.y; As[nb][lc+2][lr+64]=na1.z; As[nb][lc+3][lr+64]=na1.w;
            Bs[nb][lc+0][lr]=nb0.x; Bs[nb][lc+1][lr]=nb0.y; Bs[nb][lc+2][lr]=nb0.z; Bs[nb][lc+3][lr]=nb0.w;
            Bs[nb][lc+0][lr+64]=nb1.x; Bs[nb][lc+1][lr+64]=nb1.y; Bs[nb][lc+2][lr+64]=nb1.z; Bs[nb][lc+3][lr+64]=nb1.w;
        }
        __syncthreads();
        buf ^= 1;
    }

    float q2c[8];
#pragma unroll
    for (int jj = 0; jj < 4; jj++) q2c[jj]     = d_q2[b*SEQ + nt + nA + jj];
#pragma unroll
    for (int jj = 0; jj < 4; jj++) q2c[4 + jj] = d_q2[b*SEQ + nt + nB + jj];
    float csum[8];
#pragma unroll
    for (int jj = 0; jj < 8; jj++) csum[jj] = 0.f;
#pragma unroll
    for (int ii = 0; ii < 8; ii++) {
        float k2r = d_k2[b*SEQ + mt + m0 + ii];
        float o[8];
#pragma unroll
        for (int p = 0; p < 4; p++) {
            float2 ab = unpack2(acc2[ii][p]);
            float d2a = fmaxf(k2r + q2c[2*p]   - 2.f * ab.x, 1e-12f);
            float d2b = fmaxf(k2r + q2c[2*p+1] - 2.f * ab.y, 1e-12f);
            o[2*p]   = __expf(1.f / (1.f + __logf(1.f + sqrtf(d2a))));
            o[2*p+1] = __expf(1.f / (1.f + __logf(1.f + sqrtf(d2b))));
        }
#pragma unroll
        for (int jj = 0; jj < 8; jj++) csum[jj] += o[jj];
        float* row = d_sc + ((size_t)b*SEQ + mt + m0 + ii)*SEQ + nt;
        *(float4*)(row + nA) = make_float4(o[0], o[1], o[2], o[3]);
        *(float4*)(row + nB) = make_float4(o[4], o[5], o[6], o[7]);
    }
    *(float4*)&Ssum[ty][nA] = make_float4(csum[0], csum[1], csum[2], csum[3]);
    *(float4*)&Ssum[ty][nB] = make_float4(csum[4], csum[5], csum[6], csum[7]);
    __syncthreads();
    if (tid < 128) {
        float s = 0.f;
#pragma unroll
        for (int t = 0; t < 16; t++) s += Ssum[t][tid];
        d_part[(blockIdx.y * BATCH + b) * SEQ + nt + tid] = s;
    }
}

// ---------------- finalize colsum: 1/sum of 4 partials -----------------------
__global__ void softsum2_kernel() {
    const int i = blockIdx.x * 256 + threadIdx.x;
    float s = d_part[i] + d_part[BATCH*SEQ + i]
            + d_part[2*BATCH*SEQ + i] + d_part[3*BATCH*SEQ + i];
    d_isum[i] = 1.f / s;
}

// ---------------- out GEMM 128x128x16 over packed N=512, f32x2 ---------------
__global__ void __launch_bounds__(256, 2) out_kernel() {
    const int b  = blockIdx.z;
    const int mt = blockIdx.y * 128;
    const int nt = blockIdx.x * 128;
    const float* Ab = d_sc + (size_t)b * SEQ * SEQ;
    const float* Bb = d_vp + (size_t)b * SEQ * FP;
    const float* isum = d_isum + b * SEQ;
    __shared__ __align__(16) float As[2][16][132];
    __shared__ __align__(16) float Bs[2][16][132];
    const int tid = threadIdx.x;
    const int lr = tid >> 2, lc = (tid & 3) << 2;
    const int br = tid >> 5, bc = (tid & 31) << 2;
    const int tx = tid & 15, ty = tid >> 4;
    const int m0 = ty << 3;
    const int nA = tx << 2;
    const int nB = 64 + (tx << 2);

    u64 acc2[8][4];
#pragma unroll
    for (int ii = 0; ii < 8; ii++)
#pragma unroll
        for (int p = 0; p < 4; p++) acc2[ii][p] = 0ull;

    const float* ap0 = Ab + (size_t)(mt + lr) * SEQ + lc;
    const float* ap1 = ap0 + (size_t)64 * SEQ;
    const float* bq0 = Bb + (size_t)br * FP + nt + bc;
    const float* bq1 = bq0 + (size_t)8 * FP;

    {
        float4 a0 = *(const float4*)ap0, a1 = *(const float4*)ap1;
        float4 v0 = *(const float4*)bq0, v1 = *(const float4*)bq1;
        float s0 = isum[br], s1 = isum[br + 8];
        As[0][lc+0][lr]=a0.x; As[0][lc+1][lr]=a0.y; As[0][lc+2][lr]=a0.z; As[0][lc+3][lr]=a0.w;
        As[0][lc+0][lr+64]=a1.x; As[0][lc+1][lr+64]=a1.y; As[0][lc+2][lr+64]=a1.z; As[0][lc+3][lr+64]=a1.w;
        *(float4*)&Bs[0][br][bc]   = make_float4(v0.x*s0, v0.y*s0, v0.z*s0, v0.w*s0);
        *(float4*)&Bs[0][br+8][bc] = make_float4(v1.x*s1, v1.y*s1, v1.z*s1, v1.w*s1);
    }
    __syncthreads();

    int buf = 0;
#pragma unroll 1
    for (int kt = 0; kt < SEQ; kt += 16) {
        float4 na0, na1, nv0, nv1;
        float s0 = 0.f, s1 = 0.f;
        const bool more = (kt + 16 < SEQ);
        if (more) {
            na0 = *(const float4*)(ap0 + kt + 16);
            na1 = *(const float4*)(ap1 + kt + 16);
            nv0 = *(const float4*)(bq0 + (size_t)(kt + 16) * FP);
            nv1 = *(const float4*)(bq1 + (size_t)(kt + 16) * FP);
            s0 = isum[kt + 16 + br];
            s1 = isum[kt + 16 + br + 8];
        }
#pragma unroll
        for (int kk = 0; kk < 16; kk++) {
            float a[8];
            *(float4*)(a)     = *(const float4*)&As[buf][kk][m0];
            *(float4*)(a + 4) = *(const float4*)&As[buf][kk][m0 + 4];
            ulonglong2 bu0 = *(const ulonglong2*)&Bs[buf][kk][nA];
            ulonglong2 bu1 = *(const ulonglong2*)&Bs[buf][kk][nB];
#pragma unroll
            for (int ii = 0; ii < 8; ii++) {
                u64 a2 = dup2(a[ii]);
                FFMA2(acc2[ii][0], a2, bu0.x);
                FFMA2(acc2[ii][1], a2, bu0.y);
                FFMA2(acc2[ii][2], a2, bu1.x);
                FFMA2(acc2[ii][3], a2, bu1.y);
            }
        }
        if (more) {
            const int nb = buf ^ 1;
            As[nb][lc+0][lr]=na0.x; As[nb][lc+1][lr]=na0.y; As[nb][lc+2][lr]=na0.z; As[nb][lc+3][lr]=na0.w;
            As[nb][lc+0][lr+64]=na1.x; As[nb][lc+1][lr+64]=na1.y; As[nb][lc+2][lr+64]=na1.z; As[nb][lc+3][lr+64]=na1.w;
            *(float4*)&Bs[nb][br][bc]   = make_float4(nv0.x*s0, nv0.y*s0, nv0.z*s0, nv0.w*s0);
            *(float4*)&Bs[nb][br+8][bc] = make_float4(nv1.x*s1, nv1.y*s1, nv1.z*s1, nv1.w*s1);
        }
        __syncthreads();
        buf ^= 1;
    }

#pragma unroll
    for (int ii = 0; ii < 8; ii++) {
        float* dst = d_outp + ((size_t)b*SEQ + mt + m0 + ii)*FP + nt;
        ulonglong2 s0; s0.x = acc2[ii][0]; s0.y = acc2[ii][1];
        ulonglong2 s1; s1.x = acc2[ii][2]; s1.y = acc2[ii][3];
        *(ulonglong2*)(dst + nA) = s0;
        *(ulonglong2*)(dst + nB) = s1;
    }
}

// ---------------- unpack: packed 496 -> full symmetric 32x32, diag 0 ---------
__global__ void __launch_bounds__(256) unpack_kernel(float* __restrict__ out) {
    const int m = blockIdx.x;
    const float* src = d_outp + (size_t)m * FP;
    float* dst = out + (size_t)m * FDIM;
#pragma unroll
    for (int e = 0; e < 4; e++) {
        const int idx = threadIdx.x + e * 256;
        const int i = idx >> 5, j = idx & 31;
        float v = 0.f;
        if (i != j) {
            const int hi = (i > j) ? i : j;
            const int lo = (i > j) ? j : i;
            v = src[hi*(hi-1)/2 + lo];
        }
        dst[idx] = v;
    }
}

// ---------------- launch ----------------------------------------------------
extern "C" void kernel_launch(void* const* d_in, const int* in_sizes, int n_in,
                              void* d_out, int out_size) {
    (void)in_sizes; (void)n_in; (void)out_size;
    const float* x  = (const float*)d_in[0];
    const float* qw = (const float*)d_in[1];
    const float* kw = (const float*)d_in[2];
    const float* vw = (const float*)d_in[3];
    float* out = (float*)d_out;

    jacobi_transform_kernel<<<NMAT/4 + 1, 128>>>(x, qw, kw, vw);
    scores_kernel<<<dim3(SEQ/128, SEQ/128, BATCH), 256>>>();
    softsum2_kernel<<<BATCH*SEQ/256, 256>>>();
    out_kernel<<<dim3(FP/128, SEQ/128, BATCH), 256>>>();
    unpack_kernel<<<NMAT, 256>>>(out);
}

// round 17
// speedup vs baseline: 1.2310x; 1.0455x over previous
#include <cuda_runtime.h>
#include <math.h>

#define BATCH 16
#define SEQ   512
#define NDIM  32
#define NMAT  (BATCH*SEQ)     // 8192
#define FDIM  (NDIM*NDIM)     // 1024
#define FP    512             // padded packed feature dim
#define KEFF  496             // non-zero packed features

typedef unsigned long long u64;

// ---- packed f32x2 helpers ---------------------------------------------------
__device__ __forceinline__ u64 pack2(float lo, float hi) {
    u64 r; asm("mov.b64 %0, {%1, %2};" : "=l"(r) : "f"(lo), "f"(hi)); return r;
}
__device__ __forceinline__ u64 dup2(float v) {
    u64 r; asm("mov.b64 %0, {%1, %1};" : "=l"(r) : "f"(v)); return r;
}
__device__ __forceinline__ float2 unpack2(u64 v) {
    float2 f; asm("mov.b64 {%0, %1}, %2;" : "=f"(f.x), "=f"(f.y) : "l"(v)); return f;
}
#define FFMA2(acc, a2, b2) asm("fma.rn.f32x2 %0, %1, %2, %0;" : "+l"(acc) : "l"(a2), "l"(b2))
#define FMUL2I(g, s2)      asm("mul.rn.f32x2 %0, %0, %1;"     : "+l"(g)   : "l"(s2))
#define FADD2(d, a, b)     asm("add.rn.f32x2 %0, %1, %2;"     : "=l"(d)   : "l"(a), "l"(b))

// ---------------- scratch (static __device__, zero-initialized) ---------------
__device__ float d_qp[NMAT*FP];            // packed sqrt(2)*q lower-tri (pad 0)
__device__ float d_kp[NMAT*FP];            // packed sqrt(2)*k lower-tri (pad 0)
__device__ float d_vp[NMAT*FP];            // packed v lower-tri (pad 0)
__device__ float d_outp[NMAT*FP];          // packed output
__device__ float d_sc[BATCH*SEQ*SEQ];      // exp(scores)
__device__ float d_part[4*BATCH*SEQ];      // per-rowtile partial colsums
__device__ float d_isum[BATCH*SEQ];        // 1/colsum of exp
__device__ float d_C [3*FDIM];             // cayley matrices for q,k,v
__device__ float d_q2[NMAT];
__device__ float d_k2[NMAT];
__device__ volatile int d_cflag;           // cayley-done flag (benign replay race)

// ---------------- Cayley (one warp, one weight): C = (I-X)(I+X)^-1 ------------
__device__ void cayley_one(const float* __restrict__ W, float* __restrict__ Cout,
                           float (*Aug)[65], int lane) {
    for (int r = 0; r < 32; r++) {
        float xv = W[r*32 + lane] - W[lane*32 + r];
        float id = (r == lane) ? 1.f : 0.f;
        Aug[r][lane]      = id - xv;
        Aug[r][32 + lane] = id + xv;
    }
    __syncwarp();
    for (int kp = 0; kp < 32; kp++) {
        float ip = 1.f / Aug[kp][kp];
        __syncwarp();
        Aug[kp][lane]      *= ip;
        Aug[kp][32 + lane] *= ip;
        __syncwarp();
        for (int r = 0; r < 32; r++) {
            if (r == kp) continue;
            float f = Aug[r][kp];
            Aug[r][lane]      = fmaf(-f, Aug[kp][lane],      Aug[r][lane]);
            Aug[r][32 + lane] = fmaf(-f, Aug[kp][32 + lane], Aug[r][32 + lane]);
        }
        __syncwarp();
    }
    for (int i = 0; i < 32; i++)
        Cout[i*32 + lane] = Aug[lane][32 + i];
}

// ---------------- fused cayley + jacobi logm + transform ----------------------
#define CSTR 36
#define GT_OFF  0
#define AL_OFF  (4*32*17*8)            // 17408
#define CT_OFF  (AL_OFF + 4*32*4)      // 17920
#define SRAW_SZ (CT_OFF + 3*32*CSTR*4) // 31744
__global__ void __launch_bounds__(128, 5) jacobi_transform_kernel(
        const float* __restrict__ x,
        const float* __restrict__ qw, const float* __restrict__ kw,
        const float* __restrict__ vw) {
    __shared__ __align__(16) unsigned char sraw[SRAW_SZ];
    const int lane = threadIdx.x & 31;
    const int wip  = threadIdx.x >> 5;
    const unsigned FULL = 0xffffffffu;

    if (blockIdx.x == 0) {               // cayley block (first wave)
        if (wip < 3) {
            float (*Aug)[65] = (float(*)[65])(sraw + wip * (32*65*4));
            const float* W = (wip == 0) ? qw : (wip == 1) ? kw : vw;
            cayley_one(W, d_C + wip*FDIM, Aug, lane);
        }
        __syncthreads();
        __threadfence();
        if (threadIdx.x == 0) d_cflag = 1;
        return;
    }

    u64  (*GT)[32][17] = (u64(*)[32][17])(sraw + GT_OFF);
    float (*Al)[32]    = (float(*)[32])(sraw + AL_OFF);
    float (*Ct)[32][CSTR] = (float(*)[32][CSTR])(sraw + CT_OFF);

    const int m = (blockIdx.x - 1) * 4 + wip;
    const float* A = x + (size_t)m * FDIM;

    u64 g2[16];
#pragma unroll
    for (int r = 0; r < 16; r++)
        g2[r] = pack2(A[(2*r)*32 + lane], A[(2*r+1)*32 + lane]);

    float nrm;
    {
        u64 nA = 0ull, nB = 0ull, nC = 0ull, nD = 0ull;
#pragma unroll
        for (int r = 0; r < 4; r++) {
            FFMA2(nA, g2[r],      g2[r]);
            FFMA2(nB, g2[4 + r],  g2[4 + r]);
            FFMA2(nC, g2[8 + r],  g2[8 + r]);
            FFMA2(nD, g2[12 + r], g2[12 + r]);
        }
        u64 s; FADD2(s, nA, nB); u64 t2; FADD2(t2, nC, nD); FADD2(s, s, t2);
        float2 nf = unpack2(s);
        nrm = nf.x + nf.y;
    }
    float scale = 1.f, iscale = 1.f;

    for (int sweep = 0; sweep < 6; sweep++) {
        bool big = false;
        for (int mm = 1; mm < 32; mm++) {
            const int partner = lane ^ mm;
            u64 h2[16];
#pragma unroll
            for (int r = 0; r < 16; r++) h2[r] = __shfl_xor_sync(FULL, g2[r], mm);
            u64 dA = 0ull, dB = 0ull, dC = 0ull, dD = 0ull;
#pragma unroll
            for (int r = 0; r < 4; r++) {
                FFMA2(dA, g2[r],      h2[r]);
                FFMA2(dB, g2[4 + r],  h2[4 + r]);
                FFMA2(dC, g2[8 + r],  h2[8 + r]);
                FFMA2(dD, g2[12 + r], h2[12 + r]);
            }
            u64 ds; FADD2(ds, dA, dB); u64 dt; FADD2(dt, dC, dD); FADD2(ds, ds, dt);
            float2 df = unpack2(ds);
            float dotv = df.x + df.y;
            float nrm_o = __shfl_xor_sync(FULL, nrm,   mm);
            float sc_o  = __shfl_xor_sync(FULL, scale, mm);
            float apq = dotv * scale * sc_o;
            const bool is_p = lane < partner;
            float app = is_p ? nrm : nrm_o;
            float aqq = is_p ? nrm_o : nrm;
            float prod = app * aqq;
            float c2v  = apq * apq;      // apq^2
            big = big || (c2v > 1e-4f * prod);
            bool rot = (c2v > 1e-8f * prod);
            unsigned ball = __ballot_sync(FULL, rot);
            if (ball) {
                if (rot) {
                    // stable tangent: t = apq / (delta + sign(delta)*sqrt(delta^2+apq^2))
                    float delta = (aqq - app) * 0.5f;
                    float hyp   = sqrtf(fmaf(delta, delta, c2v));
                    float den   = delta + copysignf(hyp, delta);
                    float t     = apq / den;
                    float u     = fmaf(t, t, 1.f);
                    float cc    = rsqrtf(u);      // cos
                    float rc    = u * cc;         // 1/cos = sqrt(u), no extra MUFU
                    float spt   = is_p ? -t : t;
                    u64 c2 = dup2(spt * sc_o * iscale);
#pragma unroll
                    for (int r = 0; r < 16; r++) FFMA2(g2[r], c2, h2[r]);
                    nrm = fmaf(spt, apq, nrm);
                    scale *= cc; iscale *= rc;
                }
            }
        }
        u64 s2 = dup2(scale);
#pragma unroll
        for (int r = 0; r < 16; r++) FMUL2I(g2[r], s2);
        scale = 1.f; iscale = 1.f;
        if (!__any_sync(FULL, big)) break;
    }

    float nx;
    {
        u64 nA = 0ull, nB = 0ull, nC = 0ull, nD = 0ull;
#pragma unroll
        for (int r = 0; r < 4; r++) {
            FFMA2(nA, g2[r],      g2[r]);
            FFMA2(nB, g2[4 + r],  g2[4 + r]);
            FFMA2(nC, g2[8 + r],  g2[8 + r]);
            FFMA2(nD, g2[12 + r], g2[12 + r]);
        }
        u64 s; FADD2(s, nA, nB); u64 t2; FADD2(t2, nC, nD); FADD2(s, s, t2);
        float2 xf = unpack2(s);
        nx = xf.x + xf.y;
    }
    float alpha = 0.5f * logf(nx) / nx;

    u64* myG = &GT[wip][lane][0];
#pragma unroll
    for (int r = 0; r < 16; r++) myG[r] = g2[r];
    Al[wip][lane] = alpha;
    __syncwarp();

    u64 acc[16];
#pragma unroll
    for (int r = 0; r < 16; r++) acc[r] = 0ull;
#pragma unroll 4
    for (int t = 0; t < 32; t++) {
        const u64* col = &GT[wip][t][0];
        float2 gf = unpack2(col[lane >> 1]);
        float gelem = (lane & 1) ? gf.y : gf.x;
        u64 coef = dup2(Al[wip][t] * gelem);
#pragma unroll
        for (int r = 0; r < 16; r++) {
            u64 cv = col[r];
            FFMA2(acc[r], coef, cv);
        }
    }
    {
        float2 e = unpack2(acc[lane >> 1]);
        if (lane & 1) e.y = 0.f; else e.x = 0.f;
        acc[lane >> 1] = pack2(e.x, e.y);
    }

    if (threadIdx.x == 0) { while (d_cflag == 0) { } }
    __syncthreads();
    __threadfence();
    for (int idx = threadIdx.x; idx < 3*1024; idx += 128) {
        int w = idx >> 10, rem = idx & 1023, i = rem >> 5, k = rem & 31;
        Ct[w][k][i] = d_C[w*FDIM + i*32 + k];
    }
    __syncthreads();

    for (int w = 0; w < 3; w++) {
        u64 accT[16];
#pragma unroll
        for (int r = 0; r < 16; r++) accT[r] = 0ull;
#pragma unroll
        for (int k = 0; k < 32; k++) {
            float2 xe = unpack2(acc[k >> 1]);
            u64 c2 = dup2((k & 1) ? xe.y : xe.x);
            const ulonglong2* crow = (const ulonglong2*)&Ct[w][k][0];
#pragma unroll
            for (int p = 0; p < 8; p++) {
                ulonglong2 cv = crow[p];
                FFMA2(accT[2*p],   c2, cv.x);
                FFMA2(accT[2*p+1], c2, cv.y);
            }
        }
        __syncwarp();
#pragma unroll
        for (int r = 0; r < 16; r++) GT[wip][lane][r] = accT[r];
        __syncwarp();

        u64 acy[16];
#pragma unroll
        for (int r = 0; r < 16; r++) acy[r] = 0ull;
#pragma unroll
        for (int k = 0; k < 32; k++) {
            u64 c2 = dup2(Ct[w][k][lane]);
#pragma unroll
            for (int r = 0; r < 16; r++) {
                u64 tv = GT[wip][k][r];
                FFMA2(acy[r], c2, tv);
            }
        }

        float y[32];
#pragma unroll
        for (int r = 0; r < 16; r++) {
            float2 t = unpack2(acy[r]);
            y[2*r] = t.x; y[2*r+1] = t.y;
        }
        float* dst = (w == 0) ? d_qp : (w == 1) ? d_kp : d_vp;
        const float fac = (w < 2) ? 1.41421356237f : 1.f;
        float s = 0.f;
#pragma unroll
        for (int i = 1; i < 32; i++) {
            if (lane < i) {
                float yv = y[i];
                dst[(size_t)m*FP + i*(i-1)/2 + lane] = fac * yv;
                s = fmaf(yv, yv, s);
            }
        }
        if (w < 2) {
#pragma unroll
            for (int off = 16; off; off >>= 1) s += __shfl_down_sync(0xffffffffu, s, off);
            if (lane == 0) { if (w == 0) d_q2[m] = 2.f*s; else d_k2[m] = 2.f*s; }
        }
        __syncwarp();
    }
}

// ---------------- scores GEMM 128x128xK(496 packed), f32x2, fused colsum -----
__global__ void __launch_bounds__(256, 2) scores_kernel() {
    const int b  = blockIdx.z;
    const int mt = blockIdx.y * 128;
    const int nt = blockIdx.x * 128;
    const float* Ab = d_kp + (size_t)b * SEQ * FP;
    const float* Bb = d_qp + (size_t)b * SEQ * FP;
    __shared__ __align__(16) float As[2][16][132];
    __shared__ __align__(16) float Bs[2][16][132];
    __shared__ float Ssum[16][128];
    const int tid = threadIdx.x;
    const int lr = tid >> 2, lc = (tid & 3) << 2;
    const int tx = tid & 15, ty = tid >> 4;
    const int m0 = ty << 3;
    const int nA = tx << 2;
    const int nB = 64 + (tx << 2);

    u64 acc2[8][4];
#pragma unroll
    for (int ii = 0; ii < 8; ii++)
#pragma unroll
        for (int p = 0; p < 4; p++) acc2[ii][p] = 0ull;

    const float* ap0 = Ab + (size_t)(mt + lr) * FP + lc;
    const float* ap1 = ap0 + (size_t)64 * FP;
    const float* bp0 = Bb + (size_t)(nt + lr) * FP + lc;
    const float* bp1 = bp0 + (size_t)64 * FP;

    {
        float4 a0 = *(const float4*)ap0, a1 = *(const float4*)ap1;
        float4 b0 = *(const float4*)bp0, b1 = *(const float4*)bp1;
        As[0][lc+0][lr]=a0.x; As[0][lc+1][lr]=a0.y; As[0][lc+2][lr]=a0.z; As[0][lc+3][lr]=a0.w;
        As[0][lc+0][lr+64]=a1.x; As[0][lc+1][lr+64]=a1.y; As[0][lc+2][lr+64]=a1.z; As[0][lc+3][lr+64]=a1.w;
        Bs[0][lc+0][lr]=b0.x; Bs[0][lc+1][lr]=b0.y; Bs[0][lc+2][lr]=b0.z; Bs[0][lc+3][lr]=b0.w;
        Bs[0][lc+0][lr+64]=b1.x; Bs[0][lc+1][lr+64]=b1.y; Bs[0][lc+2][lr+64]=b1.z; Bs[0][lc+3][lr+64]=b1.w;
    }
    __syncthreads();

    int buf = 0;
#pragma unroll 1
    for (int kt = 0; kt < KEFF; kt += 16) {
        float4 na0, na1, nb0, nb1;
        const bool more = (kt + 16 < KEFF);
        if (more) {
            na0 = *(const float4*)(ap0 + kt + 16);
            na1 = *(const float4*)(ap1 + kt + 16);
            nb0 = *(const float4*)(bp0 + kt + 16);
            nb1 = *(const float4*)(bp1 + kt + 16);
        }
#pragma unroll
        for (int kk = 0; kk < 16; kk++) {
            float a[8];
            *(float4*)(a)     = *(const float4*)&As[buf][kk][m0];
            *(float4*)(a + 4) = *(const float4*)&As[buf][kk][m0 + 4];
            ulonglong2 bu0 = *(const ulonglong2*)&Bs[buf][kk][nA];
            ulonglong2 bu1 = *(const ulonglong2*)&Bs[buf][kk][nB];
#pragma unroll
            for (int ii = 0; ii < 8; ii++) {
                u64 a2 = dup2(a[ii]);
                FFMA2(acc2[ii][0], a2, bu0.x);
                FFMA2(acc2[ii][1], a2, bu0.y);
                FFMA2(acc2[ii][2], a2, bu1.x);
                FFMA2(acc2[ii][3], a2, bu1.y);
            }
        }
        if (more) {
            const int nb = buf ^ 1;
            As[nb][lc+0][lr]=na0.x; As[nb][lc+1][lr]=na0.y; As[nb][lc+2][lr]=na0.z; As[nb][lc+3][lr]=na0.w;
            As[nb][lc+0][lr+64]=na1.x; As[nb][lc+1][lr+64]=na1.y; As[nb][lc+2][lr+64]=na1.z; As[nb][lc+3][lr+64]=na1.w;
            Bs[nb][lc+0][lr]=nb0.x; Bs[nb][lc+1][lr]=nb0.y; Bs[nb][lc+2][lr]=nb0.z; Bs[nb][lc+3][lr]=nb0.w;
            Bs[nb][lc+0][lr+64]=nb1.x; Bs[nb][lc+1][lr+64]=nb1.y; Bs[nb][lc+2][lr+64]=nb1.z; Bs[nb][lc+3][lr+64]=nb1.w;
        }
        __syncthreads();
        buf ^= 1;
    }

    float q2c[8];
#pragma unroll
    for (int jj = 0; jj < 4; jj++) q2c[jj]     = d_q2[b*SEQ + nt + nA + jj];
#pragma unroll
    for (int jj = 0; jj < 4; jj++) q2c[4 + jj] = d_q2[b*SEQ + nt + nB + jj];
    float csum[8];
#pragma unroll
    for (int jj = 0; jj < 8; jj++) csum[jj] = 0.f;
#pragma unroll
    for (int ii = 0; ii < 8; ii++) {
        float k2r = d_k2[b*SEQ + mt + m0 + ii];
        float o[8];
#pragma unroll
        for (int p = 0; p < 4; p++) {
            float2 ab = unpack2(acc2[ii][p]);
            float d2a = fmaxf(k2r + q2c[2*p]   - 2.f * ab.x, 1e-12f);
            float d2b = fmaxf(k2r + q2c[2*p+1] - 2.f * ab.y, 1e-12f);
            o[2*p]   = __expf(1.f / (1.f + __logf(1.f + sqrtf(d2a))));
            o[2*p+1] = __expf(1.f / (1.f + __logf(1.f + sqrtf(d2b))));
        }
#pragma unroll
        for (int jj = 0; jj < 8; jj++) csum[jj] += o[jj];
        float* row = d_sc + ((size_t)b*SEQ + mt + m0 + ii)*SEQ + nt;
        *(float4*)(row + nA) = make_float4(o[0], o[1], o[2], o[3]);
        *(float4*)(row + nB) = make_float4(o[4], o[5], o[6], o[7]);
    }
    *(float4*)&Ssum[ty][nA] = make_float4(csum[0], csum[1], csum[2], csum[3]);
    *(float4*)&Ssum[ty][nB] = make_float4(csum[4], csum[5], csum[6], csum[7]);
    __syncthreads();
    if (tid < 128) {
        float s = 0.f;
#pragma unroll
        for (int t = 0; t < 16; t++) s += Ssum[t][tid];
        d_part[(blockIdx.y * BATCH + b) * SEQ + nt + tid] = s;
    }
}

// ---------------- finalize colsum: 1/sum of 4 partials -----------------------
__global__ void softsum2_kernel() {
    const int i = blockIdx.x * 256 + threadIdx.x;
    float s = d_part[i] + d_part[BATCH*SEQ + i]
            + d_part[2*BATCH*SEQ + i] + d_part[3*BATCH*SEQ + i];
    d_isum[i] = 1.f / s;
}

// ---------------- out GEMM 128x128x16 over packed N=512, f32x2 ---------------
__global__ void __launch_bounds__(256, 2) out_kernel() {
    const int b  = blockIdx.z;
    const int mt = blockIdx.y * 128;
    const int nt = blockIdx.x * 128;
    const float* Ab = d_sc + (size_t)b * SEQ * SEQ;
    const float* Bb = d_vp + (size_t)b * SEQ * FP;
    const float* isum = d_isum + b * SEQ;
    __shared__ __align__(16) float As[2][16][132];
    __shared__ __align__(16) float Bs[2][16][132];
    const int tid = threadIdx.x;
    const int lr = tid >> 2, lc = (tid & 3) << 2;
    const int br = tid >> 5, bc = (tid & 31) << 2;
    const int tx = tid & 15, ty = tid >> 4;
    const int m0 = ty << 3;
    const int nA = tx << 2;
    const int nB = 64 + (tx << 2);

    u64 acc2[8][4];
#pragma unroll
    for (int ii = 0; ii < 8; ii++)
#pragma unroll
        for (int p = 0; p < 4; p++) acc2[ii][p] = 0ull;

    const float* ap0 = Ab + (size_t)(mt + lr) * SEQ + lc;
    const float* ap1 = ap0 + (size_t)64 * SEQ;
    const float* bq0 = Bb + (size_t)br * FP + nt + bc;
    const float* bq1 = bq0 + (size_t)8 * FP;

    {
        float4 a0 = *(const float4*)ap0, a1 = *(const float4*)ap1;
        float4 v0 = *(const float4*)bq0, v1 = *(const float4*)bq1;
        float s0 = isum[br], s1 = isum[br + 8];
        As[0][lc+0][lr]=a0.x; As[0][lc+1][lr]=a0.y; As[0][lc+2][lr]=a0.z; As[0][lc+3][lr]=a0.w;
        As[0][lc+0][lr+64]=a1.x; As[0][lc+1][lr+64]=a1.y; As[0][lc+2][lr+64]=a1.z; As[0][lc+3][lr+64]=a1.w;
        *(float4*)&Bs[0][br][bc]   = make_float4(v0.x*s0, v0.y*s0, v0.z*s0, v0.w*s0);
        *(float4*)&Bs[0][br+8][bc] = make_float4(v1.x*s1, v1.y*s1, v1.z*s1, v1.w*s1);
    }
    __syncthreads();

    int buf = 0;
#pragma unroll 1
    for (int kt = 0; kt < SEQ; kt += 16) {
        float4 na0, na1, nv0, nv1;
        float s0 = 0.f, s1 = 0.f;
        const bool more = (kt + 16 < SEQ);
        if (more) {
            na0 = *(const float4*)(ap0 + kt + 16);
            na1 = *(const float4*)(ap1 + kt + 16);
            nv0 = *(const float4*)(bq0 + (size_t)(kt + 16) * FP);
            nv1 = *(const float4*)(bq1 + (size_t)(kt + 16) * FP);
            s0 = isum[kt + 16 + br];
            s1 = isum[kt + 16 + br + 8];
        }
#pragma unroll
        for (int kk = 0; kk < 16; kk++) {
            float a[8];
            *(float4*)(a)     = *(const float4*)&As[buf][kk][m0];
            *(float4*)(a + 4) = *(const float4*)&As[buf][kk][m0 + 4];
            ulonglong2 bu0 = *(const ulonglong2*)&Bs[buf][kk][nA];
            ulonglong2 bu1 = *(const ulonglong2*)&Bs[buf][kk][nB];
#pragma unroll
            for (int ii = 0; ii < 8; ii++) {
                u64 a2 = dup2(a[ii]);
                FFMA2(acc2[ii][0], a2, bu0.x);
                FFMA2(acc2[ii][1], a2, bu0.y);
                FFMA2(acc2[ii][2], a2, bu1.x);
                FFMA2(acc2[ii][3], a2, bu1.y);
            }
        }
        if (more) {
            const int nb = buf ^ 1;
            As[nb][lc+0][lr]=na0.x; As[nb][lc+1][lr]=na0.y; As[nb][lc+2][lr]=na0.z; As[nb][lc+3][lr]=na0.w;
            As[nb][lc+0][lr+64]=na1.x; As[nb][lc+1][lr+64]=na1.y; As[nb][lc+2][lr+64]=na1.z; As[nb][lc+3][lr+64]=na1.w;
            *(float4*)&Bs[nb][br][bc]   = make_float4(nv0.x*s0, nv0.y*s0, nv0.z*s0, nv0.w*s0);
            *(float4*)&Bs[nb][br+8][bc] = make_float4(nv1.x*s1, nv1.y*s1, nv1.z*s1, nv1.w*s1);
        }
        __syncthreads();
        buf ^= 1;
    }

#pragma unroll
    for (int ii = 0; ii < 8; ii++) {
        float* dst = d_outp + ((size_t)b*SEQ + mt + m0 + ii)*FP + nt;
        ulonglong2 s0; s0.x = acc2[ii][0]; s0.y = acc2[ii][1];
        ulonglong2 s1; s1.x = acc2[ii][2]; s1.y = acc2[ii][3];
        *(ulonglong2*)(dst + nA) = s0;
        *(ulonglong2*)(dst + nB) = s1;
    }
}

// ---------------- unpack: packed 496 -> full symmetric 32x32, diag 0 ---------
__global__ void __launch_bounds__(256) unpack_kernel(float* __restrict__ out) {
    const int m = blockIdx.x;
    const float* src = d_outp + (size_t)m * FP;
    float* dst = out + (size_t)m * FDIM;
#pragma unroll
    for (int e = 0; e < 4; e++) {
        const int idx = threadIdx.x + e * 256;
        const int i = idx >> 5, j = idx & 31;
        float v = 0.f;
        if (i != j) {
            const int hi = (i > j) ? i : j;
            const int lo = (i > j) ? j : i;
            v = src[hi*(hi-1)/2 + lo];
        }
        dst[idx] = v;
    }
}

// ---------------- launch ----------------------------------------------------
extern "C" void kernel_launch(void* const* d_in, const int* in_sizes, int n_in,
                              void* d_out, int out_size) {
    (void)in_sizes; (void)n_in; (void)out_size;
    const float* x  = (const float*)d_in[0];
    const float* qw = (const float*)d_in[1];
    const float* kw = (const float*)d_in[2];
    const float* vw = (const float*)d_in[3];
    float* out = (float*)d_out;

    jacobi_transform_kernel<<<NMAT/4 + 1, 128>>>(x, qw, kw, vw);
    scores_kernel<<<dim3(SEQ/128, SEQ/128, BATCH), 256>>>();
    softsum2_kernel<<<BATCH*SEQ/256, 256>>>();
    out_kernel<<<dim3(FP/128, SEQ/128, BATCH), 256>>>();
    unpack_kernel<<<NMAT, 256>>>(out);
}